// round 2
// baseline (speedup 1.0000x reference)
#include <cuda_runtime.h>
#include <cuda_bf16.h>
#include <math_constants.h>

// Problem constants (fixed by the dataset)
#define NN 50000                 // nodes
#define NE 800000                // raw edges
#define NT (NE + NN)             // edges + self loops = 850000
#define NEG_SLOPE 0.2f

// ---------------- scratch (device globals; no allocation allowed) ----------------
__device__ float g_h1[NN * 128];     // layer1 linear output [N,4,32]
__device__ float g_ssrc1[NN * 4];    // per-node src scores, layer1
__device__ float g_sdst1[NN * 4];    // per-node dst scores, layer1
__device__ float g_max1[NN * 4];     // segment max
__device__ float g_den1[NN * 4];     // softmax denom
__device__ float g_acc1[NN * 128];   // weighted message accumulator -> becomes out1 (relu'd)
__device__ float g_h2[NN * 64];      // layer2 linear output
__device__ float g_ssrc2[NN];
__device__ float g_sdst2[NN];
__device__ float g_max2[NN];
__device__ float g_den2[NN];
__device__ float g_acc2[NN * 64];
__device__ int   g_is64;             // edge_index dtype flag: 1 = int64, 0 = int32

// ---------------- helpers ----------------
__device__ __forceinline__ float lrelu(float v) {
    return v > 0.f ? v : NEG_SLOPE * v;
}

// float atomic max via signed/unsigned monotonic bit trick
__device__ __forceinline__ void atomicMaxF(float* addr, float v) {
    if (v >= 0.f) atomicMax((int*)addr, __float_as_int(v));
    else          atomicMin((unsigned int*)addr, __float_as_uint(v));
}

// decode edge endpoint: row = 0 (src) or 1 (dst), edge e < NE
__device__ __forceinline__ int edge_idx(const void* ei, int row, int e) {
    if (g_is64) return (int)((const long long*)ei)[(size_t)row * NE + e];
    else        return ((const int*)ei)[(size_t)row * NE + e];
}

// ---------------- dtype detection ----------------
// If edge_index is int64 (values in [0,50000)), every odd 32-bit word is 0.
// If int32, the odd words are random node ids (all-zero prob ~ (1/5e4)^128 ~= 0).
__global__ void detect_dtype(const unsigned int* __restrict__ ei_words) {
    __shared__ int any_nonzero;
    if (threadIdx.x == 0) any_nonzero = 0;
    __syncthreads();
    unsigned int w = ei_words[2 * threadIdx.x + 1];   // odd words 1,3,...,255
    if (w != 0u) atomicOr(&any_nonzero, 1);
    __syncthreads();
    if (threadIdx.x == 0) g_is64 = any_nonzero ? 0 : 1;
}

// ---------------- init ----------------
__global__ void init_kernel() {
    int i = blockIdx.x * blockDim.x + threadIdx.x;
    if (i < NN * 128) g_acc1[i] = 0.f;
    if (i < NN * 64)  g_acc2[i] = 0.f;
    if (i < NN * 4)   { g_den1[i] = 0.f; g_max1[i] = -CUDART_INF_F; }
    if (i < NN)       { g_den2[i] = 0.f; g_max2[i] = -CUDART_INF_F; }
}

// ---------------- layer1 GEMM fused with attention scores ----------------
// one warp per node row: h = x[n,:] @ W1 (128x128), scores s_src/s_dst per head.
__global__ void gemm1_kernel(const float* __restrict__ x,
                             const float* __restrict__ W,
                             const float* __restrict__ a_src,
                             const float* __restrict__ a_dst) {
    __shared__ float xs[8][128];
    int w = threadIdx.x >> 5;
    int l = threadIdx.x & 31;
    int n = blockIdx.x * 8 + w;
    if (n >= NN) return;

    // stage this warp's input row in shared
    ((float4*)xs[w])[l] = ((const float4*)(x + (size_t)n * 128))[l];
    __syncwarp();

    float4 acc = make_float4(0.f, 0.f, 0.f, 0.f);
    const float4* Wr = (const float4*)W;   // row k, cols [4l,4l+4): Wr[k*32 + l]
#pragma unroll 8
    for (int k = 0; k < 128; k++) {
        float xv = xs[w][k];
        float4 wv = Wr[k * 32 + l];
        acc.x = fmaf(xv, wv.x, acc.x);
        acc.y = fmaf(xv, wv.y, acc.y);
        acc.z = fmaf(xv, wv.z, acc.z);
        acc.w = fmaf(xv, wv.w, acc.w);
    }
    ((float4*)(g_h1 + (size_t)n * 128))[l] = acc;

    // attention scores: head h = l/8 owns cols [h*32, h*32+32); this lane holds 4 of them
    int h   = l >> 3;
    int off = (l & 7) * 4;
    float4 as = *(const float4*)(a_src + h * 32 + off);
    float4 ad = *(const float4*)(a_dst + h * 32 + off);
    float ps = acc.x * as.x + acc.y * as.y + acc.z * as.z + acc.w * as.w;
    float pd = acc.x * ad.x + acc.y * ad.y + acc.z * ad.z + acc.w * ad.w;
#pragma unroll
    for (int m = 1; m < 8; m <<= 1) {
        ps += __shfl_xor_sync(0xffffffff, ps, m);
        pd += __shfl_xor_sync(0xffffffff, pd, m);
    }
    if ((l & 7) == 0) {
        g_ssrc1[n * 4 + h] = ps;
        g_sdst1[n * 4 + h] = pd;
    }
}

// ---------------- layer1 edge pass A: segment max ----------------
__global__ void edge_max1(const void* __restrict__ ei) {
    int e = blockIdx.x * blockDim.x + threadIdx.x;
    if (e >= NT) return;
    int s, d;
    if (e < NE) { s = edge_idx(ei, 0, e); d = edge_idx(ei, 1, e); }
    else        { s = e - NE; d = s; }
    float4 ss = *(const float4*)(g_ssrc1 + s * 4);
    float4 sd = *(const float4*)(g_sdst1 + d * 4);
    atomicMaxF(&g_max1[d * 4 + 0], lrelu(ss.x + sd.x));
    atomicMaxF(&g_max1[d * 4 + 1], lrelu(ss.y + sd.y));
    atomicMaxF(&g_max1[d * 4 + 2], lrelu(ss.z + sd.z));
    atomicMaxF(&g_max1[d * 4 + 3], lrelu(ss.w + sd.w));
}

// ---------------- layer1 edge pass B: exp + denom + weighted message accumulate ----------------
// one warp per edge; lane l handles channel l of each of the 4 heads.
__global__ void edge_acc1(const void* __restrict__ ei) {
    int e = blockIdx.x * 8 + (threadIdx.x >> 5);
    int l = threadIdx.x & 31;
    if (e >= NT) return;
    int s, d;
    if (e < NE) { s = edge_idx(ei, 0, e); d = edge_idx(ei, 1, e); }
    else        { s = e - NE; d = s; }

    float4 ss = *(const float4*)(g_ssrc1 + s * 4);
    float4 sd = *(const float4*)(g_sdst1 + d * 4);
    float4 mx = *(const float4*)(g_max1 + d * 4);
    float4 p;
    p.x = __expf(lrelu(ss.x + sd.x) - mx.x);
    p.y = __expf(lrelu(ss.y + sd.y) - mx.y);
    p.z = __expf(lrelu(ss.z + sd.z) - mx.z);
    p.w = __expf(lrelu(ss.w + sd.w) - mx.w);

    if (l < 4) {
        float pl = (l == 0) ? p.x : (l == 1) ? p.y : (l == 2) ? p.z : p.w;
        atomicAdd(&g_den1[d * 4 + l], pl);
    }
    const float* hs = g_h1 + (size_t)s * 128;
    float* ad = g_acc1 + (size_t)d * 128;
    atomicAdd(ad + l,      p.x * hs[l]);
    atomicAdd(ad + 32 + l, p.y * hs[32 + l]);
    atomicAdd(ad + 64 + l, p.z * hs[64 + l]);
    atomicAdd(ad + 96 + l, p.w * hs[96 + l]);
}

// ---------------- layer1 finalize: normalize + bias + ReLU (in place) ----------------
__global__ void finalize1(const float* __restrict__ bias) {
    int i = blockIdx.x * blockDim.x + threadIdx.x;
    if (i >= NN * 128) return;
    int n = i >> 7;
    int c = i & 127;
    int h = c >> 5;
    float v = g_acc1[i] / g_den1[n * 4 + h] + bias[c];
    g_acc1[i] = fmaxf(v, 0.f);
}

// ---------------- layer2 GEMM fused with scores (1 head) ----------------
__global__ void gemm2_kernel(const float* __restrict__ W,
                             const float* __restrict__ a_src,
                             const float* __restrict__ a_dst) {
    __shared__ float xs[8][128];
    int w = threadIdx.x >> 5;
    int l = threadIdx.x & 31;
    int n = blockIdx.x * 8 + w;
    if (n >= NN) return;

    ((float4*)xs[w])[l] = ((const float4*)(g_acc1 + (size_t)n * 128))[l];
    __syncwarp();

    float2 acc = make_float2(0.f, 0.f);
    const float2* Wr = (const float2*)W;   // row k, cols [2l,2l+2): Wr[k*32 + l]
#pragma unroll 8
    for (int k = 0; k < 128; k++) {
        float xv = xs[w][k];
        float2 wv = Wr[k * 32 + l];
        acc.x = fmaf(xv, wv.x, acc.x);
        acc.y = fmaf(xv, wv.y, acc.y);
    }
    ((float2*)(g_h2 + (size_t)n * 64))[l] = acc;

    float2 as = *(const float2*)(a_src + 2 * l);
    float2 ad = *(const float2*)(a_dst + 2 * l);
    float ps = acc.x * as.x + acc.y * as.y;
    float pd = acc.x * ad.x + acc.y * ad.y;
#pragma unroll
    for (int m = 1; m < 32; m <<= 1) {
        ps += __shfl_xor_sync(0xffffffff, ps, m);
        pd += __shfl_xor_sync(0xffffffff, pd, m);
    }
    if (l == 0) {
        g_ssrc2[n] = ps;
        g_sdst2[n] = pd;
    }
}

// ---------------- layer2 edge pass A ----------------
__global__ void edge_max2(const void* __restrict__ ei) {
    int e = blockIdx.x * blockDim.x + threadIdx.x;
    if (e >= NT) return;
    int s, d;
    if (e < NE) { s = edge_idx(ei, 0, e); d = edge_idx(ei, 1, e); }
    else        { s = e - NE; d = s; }
    atomicMaxF(&g_max2[d], lrelu(g_ssrc2[s] + g_sdst2[d]));
}

// ---------------- layer2 edge pass B ----------------
// one warp per edge; lane l handles channels l and l+32.
__global__ void edge_acc2(const void* __restrict__ ei) {
    int e = blockIdx.x * 8 + (threadIdx.x >> 5);
    int l = threadIdx.x & 31;
    if (e >= NT) return;
    int s, d;
    if (e < NE) { s = edge_idx(ei, 0, e); d = edge_idx(ei, 1, e); }
    else        { s = e - NE; d = s; }

    float p = __expf(lrelu(g_ssrc2[s] + g_sdst2[d]) - g_max2[d]);
    if (l == 0) atomicAdd(&g_den2[d], p);
    const float* hs = g_h2 + (size_t)s * 64;
    float* ad = g_acc2 + (size_t)d * 64;
    atomicAdd(ad + l,      p * hs[l]);
    atomicAdd(ad + 32 + l, p * hs[32 + l]);
}

// ---------------- layer2 finalize -> output ----------------
__global__ void finalize2(const float* __restrict__ bias, float* __restrict__ out) {
    int i = blockIdx.x * blockDim.x + threadIdx.x;
    if (i >= NN * 64) return;
    int n = i >> 6;
    int c = i & 63;
    out[i] = g_acc2[i] / g_den2[n] + bias[c];
}

// ---------------- launch ----------------
extern "C" void kernel_launch(void* const* d_in, const int* in_sizes, int n_in,
                              void* d_out, int out_size) {
    const float* x     = (const float*)d_in[0];
    const void*  ei    = d_in[1];
    const float* W1    = (const float*)d_in[2];
    const float* asrc1 = (const float*)d_in[3];
    const float* adst1 = (const float*)d_in[4];
    const float* b1    = (const float*)d_in[5];
    const float* W2    = (const float*)d_in[6];
    const float* asrc2 = (const float*)d_in[7];
    const float* adst2 = (const float*)d_in[8];
    const float* b2    = (const float*)d_in[9];
    float* out = (float*)d_out;

    const int T = 256;
    detect_dtype<<<1, 128>>>((const unsigned int*)ei);
    init_kernel<<<(NN * 128 + T - 1) / T, T>>>();
    gemm1_kernel<<<(NN + 7) / 8, 256>>>(x, W1, asrc1, adst1);
    edge_max1<<<(NT + T - 1) / T, T>>>(ei);
    edge_acc1<<<(NT + 7) / 8, 256>>>(ei);
    finalize1<<<(NN * 128 + T - 1) / T, T>>>(b1);
    gemm2_kernel<<<(NN + 7) / 8, 256>>>(W2, asrc2, adst2);
    edge_max2<<<(NT + T - 1) / T, T>>>(ei);
    edge_acc2<<<(NT + 7) / 8, 256>>>(ei);
    finalize2<<<(NN * 64 + T - 1) / T, T>>>(b2, out);
}

// round 3
// speedup vs baseline: 1.7650x; 1.7650x over previous
#include <cuda_runtime.h>
#include <cuda_bf16.h>
#include <math_constants.h>

#define NN 50000                 // nodes
#define NE 800000                // raw edges
#define NT (NE + NN)             // edges + self loops
#define NEG_SLOPE 0.2f

// ---------------- scratch ----------------
__device__ float g_h1[NN * 128];     // layer1 linear output [N,4,32]
__device__ float g_ssrc1[NN * 4];
__device__ float g_sdst1[NN * 4];
__device__ float g_out1[NN * 128];   // layer1 output (relu'd)
__device__ float g_h2[NN * 64];
__device__ float g_ssrc2[NN];
__device__ float g_sdst2[NN];
__device__ int   g_cnt[NN];
__device__ int   g_rowptr[NN + 1];
__device__ int   g_cursor[NN];
__device__ int   g_csr_src[NT];
__device__ int   g_is64;

// ---------------- helpers ----------------
__device__ __forceinline__ float lrelu(float v) { return v > 0.f ? v : NEG_SLOPE * v; }

__device__ __forceinline__ int edge_idx(const void* ei, int row, int e) {
    if (g_is64) return (int)((const long long*)ei)[(size_t)row * NE + e];
    else        return ((const int*)ei)[(size_t)row * NE + e];
}

// ---------------- dtype detection ----------------
__global__ void detect_dtype(const unsigned int* __restrict__ ei_words) {
    __shared__ int any_nonzero;
    if (threadIdx.x == 0) any_nonzero = 0;
    __syncthreads();
    unsigned int w = ei_words[2 * threadIdx.x + 1];
    if (w != 0u) atomicOr(&any_nonzero, 1);
    __syncthreads();
    if (threadIdx.x == 0) g_is64 = any_nonzero ? 0 : 1;
}

// ---------------- CSR build ----------------
__global__ void zero_cnt() {
    int i = blockIdx.x * blockDim.x + threadIdx.x;
    if (i < NN) g_cnt[i] = 0;
}

__global__ void hist_kernel(const void* __restrict__ ei) {
    int e = blockIdx.x * blockDim.x + threadIdx.x;
    if (e >= NT) return;
    int d = (e < NE) ? edge_idx(ei, 1, e) : (e - NE);
    atomicAdd(&g_cnt[d], 1);
}

// single-block exclusive scan over g_cnt -> g_rowptr, g_cursor
__global__ void scan_kernel() {
    __shared__ int warp_sums[32];
    __shared__ int s_running;
    int t = threadIdx.x;                 // 1024 threads
    if (t == 0) s_running = 0;
    __syncthreads();
    for (int base = 0; base < NN; base += 1024) {
        int idx = base + t;
        int v = (idx < NN) ? g_cnt[idx] : 0;
        int incl = v;
#pragma unroll
        for (int o = 1; o < 32; o <<= 1) {
            int nbr = __shfl_up_sync(0xffffffff, incl, o);
            if ((t & 31) >= o) incl += nbr;
        }
        if ((t & 31) == 31) warp_sums[t >> 5] = incl;
        __syncthreads();
        if (t < 32) {
            int ws = warp_sums[t];
            int wincl = ws;
#pragma unroll
            for (int o = 1; o < 32; o <<= 1) {
                int nbr = __shfl_up_sync(0xffffffff, wincl, o);
                if (t >= o) wincl += nbr;
            }
            warp_sums[t] = wincl - ws;   // exclusive warp offset
        }
        __syncthreads();
        int excl = incl - v + warp_sums[t >> 5] + s_running;
        if (idx < NN) { g_rowptr[idx] = excl; g_cursor[idx] = excl; }
        __syncthreads();
        if (t == 1023) s_running = excl + v;
        __syncthreads();
    }
    if (t == 0) g_rowptr[NN] = s_running;
}

__global__ void scatter_kernel(const void* __restrict__ ei) {
    int e = blockIdx.x * blockDim.x + threadIdx.x;
    if (e >= NT) return;
    int s, d;
    if (e < NE) { s = edge_idx(ei, 0, e); d = edge_idx(ei, 1, e); }
    else        { s = e - NE; d = s; }
    int pos = atomicAdd(&g_cursor[d], 1);
    g_csr_src[pos] = s;
}

// ---------------- layer1 GEMM (4 nodes per warp) fused with scores ----------------
__global__ void gemm1_kernel(const float* __restrict__ x,
                             const float* __restrict__ W,
                             const float* __restrict__ a_src,
                             const float* __restrict__ a_dst) {
    __shared__ float xs[32][128];        // 16KB
    int w = threadIdx.x >> 5;
    int l = threadIdx.x & 31;
    int n0 = blockIdx.x * 32 + w * 4;

#pragma unroll
    for (int j = 0; j < 4; j++) {
        int n = n0 + j;
        if (n < NN) ((float4*)xs[w * 4 + j])[l] = ((const float4*)(x + (size_t)n * 128))[l];
    }
    __syncwarp();
    if (n0 >= NN) return;

    float4 acc[4] = {};
    const float4* Wr = (const float4*)W;
#pragma unroll 4
    for (int k = 0; k < 128; k++) {
        float4 wv = Wr[k * 32 + l];
#pragma unroll
        for (int j = 0; j < 4; j++) {
            float xv = xs[w * 4 + j][k];
            acc[j].x = fmaf(xv, wv.x, acc[j].x);
            acc[j].y = fmaf(xv, wv.y, acc[j].y);
            acc[j].z = fmaf(xv, wv.z, acc[j].z);
            acc[j].w = fmaf(xv, wv.w, acc[j].w);
        }
    }

    int h   = l >> 3;
    int off = (l & 7) * 4;
    float4 as = *(const float4*)(a_src + h * 32 + off);
    float4 ad = *(const float4*)(a_dst + h * 32 + off);

#pragma unroll
    for (int j = 0; j < 4; j++) {
        int n = n0 + j;
        if (n >= NN) break;
        ((float4*)(g_h1 + (size_t)n * 128))[l] = acc[j];
        float ps = acc[j].x * as.x + acc[j].y * as.y + acc[j].z * as.z + acc[j].w * as.w;
        float pd = acc[j].x * ad.x + acc[j].y * ad.y + acc[j].z * ad.z + acc[j].w * ad.w;
#pragma unroll
        for (int m = 1; m < 8; m <<= 1) {
            ps += __shfl_xor_sync(0xffffffff, ps, m);
            pd += __shfl_xor_sync(0xffffffff, pd, m);
        }
        if ((l & 7) == 0) {
            g_ssrc1[n * 4 + h] = ps;
            g_sdst1[n * 4 + h] = pd;
        }
    }
}

// ---------------- layer1 fused softmax + aggregation + finalize (warp per node) ----------------
__global__ void agg1_kernel(const float* __restrict__ bias) {
    int w = threadIdx.x >> 5;
    int l = threadIdx.x & 31;
    int d = blockIdx.x * 8 + w;
    if (d >= NN) return;
    int start = g_rowptr[d];
    int end   = g_rowptr[d + 1];
    float4 sd = *(const float4*)(g_sdst1 + d * 4);

    // phase A: segment max per head
    float4 m = make_float4(-CUDART_INF_F, -CUDART_INF_F, -CUDART_INF_F, -CUDART_INF_F);
    for (int i = start + l; i < end; i += 32) {
        int s = g_csr_src[i];
        float4 ss = *(const float4*)(g_ssrc1 + s * 4);
        m.x = fmaxf(m.x, lrelu(ss.x + sd.x));
        m.y = fmaxf(m.y, lrelu(ss.y + sd.y));
        m.z = fmaxf(m.z, lrelu(ss.z + sd.z));
        m.w = fmaxf(m.w, lrelu(ss.w + sd.w));
    }
#pragma unroll
    for (int o = 16; o; o >>= 1) {
        m.x = fmaxf(m.x, __shfl_xor_sync(0xffffffff, m.x, o));
        m.y = fmaxf(m.y, __shfl_xor_sync(0xffffffff, m.y, o));
        m.z = fmaxf(m.z, __shfl_xor_sync(0xffffffff, m.z, o));
        m.w = fmaxf(m.w, __shfl_xor_sync(0xffffffff, m.w, o));
    }

    // phase B: exp + denom + weighted accumulate (lane l owns channels l,32+l,64+l,96+l)
    float a0 = 0.f, a1 = 0.f, a2 = 0.f, a3 = 0.f;
    float4 den = make_float4(0.f, 0.f, 0.f, 0.f);
    for (int base = start; base < end; base += 32) {
        int i = base + l;
        int s_l = 0;
        float4 p_l = make_float4(0.f, 0.f, 0.f, 0.f);
        if (i < end) {
            s_l = g_csr_src[i];
            float4 ss = *(const float4*)(g_ssrc1 + s_l * 4);
            p_l.x = __expf(lrelu(ss.x + sd.x) - m.x);
            p_l.y = __expf(lrelu(ss.y + sd.y) - m.y);
            p_l.z = __expf(lrelu(ss.z + sd.z) - m.z);
            p_l.w = __expf(lrelu(ss.w + sd.w) - m.w);
            den.x += p_l.x; den.y += p_l.y; den.z += p_l.z; den.w += p_l.w;
        }
        int cnt = min(32, end - base);
        for (int j = 0; j < cnt; j++) {
            int   s  = __shfl_sync(0xffffffff, s_l, j);
            float px = __shfl_sync(0xffffffff, p_l.x, j);
            float py = __shfl_sync(0xffffffff, p_l.y, j);
            float pz = __shfl_sync(0xffffffff, p_l.z, j);
            float pw = __shfl_sync(0xffffffff, p_l.w, j);
            const float* hs = g_h1 + (size_t)s * 128;
            a0 = fmaf(px, hs[l],      a0);
            a1 = fmaf(py, hs[32 + l], a1);
            a2 = fmaf(pz, hs[64 + l], a2);
            a3 = fmaf(pw, hs[96 + l], a3);
        }
    }
#pragma unroll
    for (int o = 16; o; o >>= 1) {
        den.x += __shfl_xor_sync(0xffffffff, den.x, o);
        den.y += __shfl_xor_sync(0xffffffff, den.y, o);
        den.z += __shfl_xor_sync(0xffffffff, den.z, o);
        den.w += __shfl_xor_sync(0xffffffff, den.w, o);
    }

    float* od = g_out1 + (size_t)d * 128;
    od[l]      = fmaxf(a0 / den.x + bias[l],      0.f);
    od[32 + l] = fmaxf(a1 / den.y + bias[32 + l], 0.f);
    od[64 + l] = fmaxf(a2 / den.z + bias[64 + l], 0.f);
    od[96 + l] = fmaxf(a3 / den.w + bias[96 + l], 0.f);
}

// ---------------- layer2 GEMM (4 nodes per warp) fused with scores ----------------
__global__ void gemm2_kernel(const float* __restrict__ W,
                             const float* __restrict__ a_src,
                             const float* __restrict__ a_dst) {
    __shared__ float xs[32][128];
    int w = threadIdx.x >> 5;
    int l = threadIdx.x & 31;
    int n0 = blockIdx.x * 32 + w * 4;

#pragma unroll
    for (int j = 0; j < 4; j++) {
        int n = n0 + j;
        if (n < NN) ((float4*)xs[w * 4 + j])[l] = ((const float4*)(g_out1 + (size_t)n * 128))[l];
    }
    __syncwarp();
    if (n0 >= NN) return;

    float2 acc[4] = {};
    const float2* Wr = (const float2*)W;
#pragma unroll 4
    for (int k = 0; k < 128; k++) {
        float2 wv = Wr[k * 32 + l];
#pragma unroll
        for (int j = 0; j < 4; j++) {
            float xv = xs[w * 4 + j][k];
            acc[j].x = fmaf(xv, wv.x, acc[j].x);
            acc[j].y = fmaf(xv, wv.y, acc[j].y);
        }
    }

    float2 as = *(const float2*)(a_src + 2 * l);
    float2 ad = *(const float2*)(a_dst + 2 * l);
#pragma unroll
    for (int j = 0; j < 4; j++) {
        int n = n0 + j;
        if (n >= NN) break;
        ((float2*)(g_h2 + (size_t)n * 64))[l] = acc[j];
        float ps = acc[j].x * as.x + acc[j].y * as.y;
        float pd = acc[j].x * ad.x + acc[j].y * ad.y;
#pragma unroll
        for (int m = 1; m < 32; m <<= 1) {
            ps += __shfl_xor_sync(0xffffffff, ps, m);
            pd += __shfl_xor_sync(0xffffffff, pd, m);
        }
        if (l == 0) {
            g_ssrc2[n] = ps;
            g_sdst2[n] = pd;
        }
    }
}

// ---------------- layer2 fused softmax + aggregation -> output ----------------
__global__ void agg2_kernel(const float* __restrict__ bias, float* __restrict__ out) {
    int w = threadIdx.x >> 5;
    int l = threadIdx.x & 31;
    int d = blockIdx.x * 8 + w;
    if (d >= NN) return;
    int start = g_rowptr[d];
    int end   = g_rowptr[d + 1];
    float sdv = g_sdst2[d];

    float m = -CUDART_INF_F;
    for (int i = start + l; i < end; i += 32) {
        int s = g_csr_src[i];
        m = fmaxf(m, lrelu(g_ssrc2[s] + sdv));
    }
#pragma unroll
    for (int o = 16; o; o >>= 1) m = fmaxf(m, __shfl_xor_sync(0xffffffff, m, o));

    float a0 = 0.f, a1 = 0.f, den = 0.f;
    for (int base = start; base < end; base += 32) {
        int i = base + l;
        int s_l = 0;
        float p_l = 0.f;
        if (i < end) {
            s_l = g_csr_src[i];
            p_l = __expf(lrelu(g_ssrc2[s_l] + sdv) - m);
            den += p_l;
        }
        int cnt = min(32, end - base);
        for (int j = 0; j < cnt; j++) {
            int   s = __shfl_sync(0xffffffff, s_l, j);
            float p = __shfl_sync(0xffffffff, p_l, j);
            const float* hs = g_h2 + (size_t)s * 64;
            a0 = fmaf(p, hs[l],      a0);
            a1 = fmaf(p, hs[32 + l], a1);
        }
    }
#pragma unroll
    for (int o = 16; o; o >>= 1) den += __shfl_xor_sync(0xffffffff, den, o);

    out[(size_t)d * 64 + l]      = a0 / den + bias[l];
    out[(size_t)d * 64 + 32 + l] = a1 / den + bias[32 + l];
}

// ---------------- launch ----------------
extern "C" void kernel_launch(void* const* d_in, const int* in_sizes, int n_in,
                              void* d_out, int out_size) {
    const float* x     = (const float*)d_in[0];
    const void*  ei    = d_in[1];
    const float* W1    = (const float*)d_in[2];
    const float* asrc1 = (const float*)d_in[3];
    const float* adst1 = (const float*)d_in[4];
    const float* b1    = (const float*)d_in[5];
    const float* W2    = (const float*)d_in[6];
    const float* asrc2 = (const float*)d_in[7];
    const float* adst2 = (const float*)d_in[8];
    const float* b2    = (const float*)d_in[9];
    float* out = (float*)d_out;

    const int T = 256;
    detect_dtype<<<1, 128>>>((const unsigned int*)ei);
    zero_cnt<<<(NN + T - 1) / T, T>>>();
    hist_kernel<<<(NT + T - 1) / T, T>>>(ei);
    scan_kernel<<<1, 1024>>>();
    scatter_kernel<<<(NT + T - 1) / T, T>>>(ei);
    gemm1_kernel<<<(NN + 31) / 32, 256>>>(x, W1, asrc1, adst1);
    agg1_kernel<<<(NN + 7) / 8, 256>>>(b1);
    gemm2_kernel<<<(NN + 31) / 32, 256>>>(W2, asrc2, adst2);
    agg2_kernel<<<(NN + 7) / 8, 256>>>(b2, out);
}

// round 4
// speedup vs baseline: 1.9269x; 1.0917x over previous
#include <cuda_runtime.h>
#include <cuda_bf16.h>
#include <math_constants.h>

#define NN 50000                 // nodes
#define NE 800000                // raw edges
#define NT (NE + NN)             // edges + self loops
#define NEG_SLOPE 0.2f
#define NB_SCAN ((NN + 1023) / 1024)   // 49 scan blocks

// ---------------- scratch ----------------
__device__ float g_h1[NN * 128];
__device__ float g_ssrc1[NN * 4];
__device__ float g_sdst1[NN * 4];
__device__ float g_out1[NN * 128];
__device__ float g_h2[NN * 64];
__device__ float g_ssrc2[NN];
__device__ float g_sdst2[NN];
__device__ int   g_cnt[NN];
__device__ int   g_rowptr[NN + 1];
__device__ int   g_cursor[NN];
__device__ int   g_csr_src[NT];
__device__ int   g_bsum[64];
__device__ int   g_boff[64];
__device__ int   g_is64;

// ---------------- helpers ----------------
__device__ __forceinline__ float lrelu(float v) { return v > 0.f ? v : NEG_SLOPE * v; }

__device__ __forceinline__ int edge_idx(const void* ei, int row, int e) {
    if (g_is64) return (int)((const long long*)ei)[(size_t)row * NE + e];
    else        return ((const int*)ei)[(size_t)row * NE + e];
}

// packed f32x2 helpers (Blackwell FFMA2 — only via PTX)
__device__ __forceinline__ unsigned long long pack2(float f) {
    unsigned long long r;
    asm("mov.b64 %0, {%1, %1};" : "=l"(r) : "f"(f));
    return r;
}
__device__ __forceinline__ unsigned long long fma2(unsigned long long a,
                                                   unsigned long long b,
                                                   unsigned long long c) {
    unsigned long long d;
    asm("fma.rn.f32x2 %0, %1, %2, %3;" : "=l"(d) : "l"(a), "l"(b), "l"(c));
    return d;
}
__device__ __forceinline__ void unpack2(unsigned long long v, float& lo, float& hi) {
    asm("mov.b64 {%0, %1}, %2;" : "=f"(lo), "=f"(hi) : "l"(v));
}

// ---------------- dtype detection ----------------
__global__ void detect_dtype(const unsigned int* __restrict__ ei_words) {
    __shared__ int any_nonzero;
    if (threadIdx.x == 0) any_nonzero = 0;
    __syncthreads();
    unsigned int w = ei_words[2 * threadIdx.x + 1];
    if (w != 0u) atomicOr(&any_nonzero, 1);
    __syncthreads();
    if (threadIdx.x == 0) g_is64 = any_nonzero ? 0 : 1;
}

// ---------------- CSR build ----------------
__global__ void zero_cnt() {
    int i = blockIdx.x * blockDim.x + threadIdx.x;
    if (i < NN) g_cnt[i] = 0;
}

__global__ void hist_kernel(const void* __restrict__ ei) {
    int e = blockIdx.x * blockDim.x + threadIdx.x;
    if (e >= NT) return;
    int d = (e < NE) ? edge_idx(ei, 1, e) : (e - NE);
    atomicAdd(&g_cnt[d], 1);
}

// scan phase 1: per-block (1024) exclusive scan, block totals to g_bsum
__global__ void scan1_kernel() {
    __shared__ int wsum[32];
    int t = threadIdx.x;
    int idx = blockIdx.x * 1024 + t;
    int v = (idx < NN) ? g_cnt[idx] : 0;
    int incl = v;
#pragma unroll
    for (int o = 1; o < 32; o <<= 1) {
        int nbr = __shfl_up_sync(0xffffffff, incl, o);
        if ((t & 31) >= o) incl += nbr;
    }
    if ((t & 31) == 31) wsum[t >> 5] = incl;
    __syncthreads();
    if (t < 32) {
        int ws = wsum[t];
        int wincl = ws;
#pragma unroll
        for (int o = 1; o < 32; o <<= 1) {
            int nbr = __shfl_up_sync(0xffffffff, wincl, o);
            if (t >= o) wincl += nbr;
        }
        wsum[t] = wincl - ws;
    }
    __syncthreads();
    int excl = incl - v + wsum[t >> 5];
    if (idx < NN) g_rowptr[idx] = excl;              // local (pre-offset)
    if (t == 1023) g_bsum[blockIdx.x] = excl + v;    // block total
}

// scan phase 2: scan the (<=64) block sums
__global__ void scan2_kernel() {
    __shared__ int s[64];
    int t = threadIdx.x;   // 64 threads
    int v = (t < NB_SCAN) ? g_bsum[t] : 0;
    s[t] = v;
    __syncthreads();
#pragma unroll
    for (int o = 1; o < 64; o <<= 1) {
        int tmp = (t >= o) ? s[t - o] : 0;
        __syncthreads();
        s[t] += tmp;
        __syncthreads();
    }
    g_boff[t] = s[t] - v;   // exclusive
}

// scan phase 3: add block offsets, init cursor, set rowptr[NN]
__global__ void scan3_kernel() {
    int idx = blockIdx.x * blockDim.x + threadIdx.x;
    if (idx == 0) g_rowptr[NN] = NT;
    if (idx >= NN) return;
    int r = g_rowptr[idx] + g_boff[idx >> 10];
    g_rowptr[idx] = r;
    g_cursor[idx] = r;
}

__global__ void scatter_kernel(const void* __restrict__ ei) {
    int e = blockIdx.x * blockDim.x + threadIdx.x;
    if (e >= NT) return;
    int s, d;
    if (e < NE) { s = edge_idx(ei, 0, e); d = edge_idx(ei, 1, e); }
    else        { s = e - NE; d = s; }
    int pos = atomicAdd(&g_cursor[d], 1);
    g_csr_src[pos] = s;
}

// ---------------- layer1 GEMM (4 nodes/warp, f32x2) fused with scores ----------------
__global__ void gemm1_kernel(const float* __restrict__ x,
                             const float* __restrict__ W,
                             const float* __restrict__ a_src,
                             const float* __restrict__ a_dst) {
    __shared__ unsigned long long xs2[32][128];   // duplicated {x,x} pairs, 32KB
    int w = threadIdx.x >> 5;
    int l = threadIdx.x & 31;
    int n0 = blockIdx.x * 32 + w * 4;

#pragma unroll
    for (int j = 0; j < 4; j++) {
        int n = n0 + j;
        if (n < NN) {
            float4 v = ((const float4*)(x + (size_t)n * 128))[l];
            unsigned long long* row = xs2[w * 4 + j] + 4 * l;
            row[0] = pack2(v.x); row[1] = pack2(v.y);
            row[2] = pack2(v.z); row[3] = pack2(v.w);
        }
    }
    __syncwarp();
    if (n0 >= NN) return;

    unsigned long long acc01[4] = {}, acc23[4] = {};
    const ulonglong2* Wr = (const ulonglong2*)W;   // row k: cols [4l,4l+4) as 2 packed pairs
#pragma unroll 4
    for (int k = 0; k < 128; k++) {
        ulonglong2 wv = Wr[k * 32 + l];
#pragma unroll
        for (int j = 0; j < 4; j++) {
            unsigned long long xv = xs2[w * 4 + j][k];
            acc01[j] = fma2(xv, wv.x, acc01[j]);
            acc23[j] = fma2(xv, wv.y, acc23[j]);
        }
    }

    int h   = l >> 3;
    int off = (l & 7) * 4;
    float4 as = *(const float4*)(a_src + h * 32 + off);
    float4 ad = *(const float4*)(a_dst + h * 32 + off);

#pragma unroll
    for (int j = 0; j < 4; j++) {
        int n = n0 + j;
        if (n >= NN) break;
        ulonglong2 st; st.x = acc01[j]; st.y = acc23[j];
        ((ulonglong2*)(g_h1 + (size_t)n * 128))[l] = st;
        float ax, ay, az, aw;
        unpack2(acc01[j], ax, ay);
        unpack2(acc23[j], az, aw);
        float ps = ax * as.x + ay * as.y + az * as.z + aw * as.w;
        float pd = ax * ad.x + ay * ad.y + az * ad.z + aw * ad.w;
#pragma unroll
        for (int m = 1; m < 8; m <<= 1) {
            ps += __shfl_xor_sync(0xffffffff, ps, m);
            pd += __shfl_xor_sync(0xffffffff, pd, m);
        }
        if ((l & 7) == 0) {
            g_ssrc1[n * 4 + h] = ps;
            g_sdst1[n * 4 + h] = pd;
        }
    }
}

// ---------------- layer1 fused softmax + aggregation + finalize (warp per node) ----------------
__global__ void agg1_kernel(const float* __restrict__ bias) {
    int w = threadIdx.x >> 5;
    int l = threadIdx.x & 31;
    int d = blockIdx.x * 8 + w;
    if (d >= NN) return;
    int start = g_rowptr[d];
    int end   = g_rowptr[d + 1];
    float4 sd = *(const float4*)(g_sdst1 + d * 4);

    float4 m = make_float4(-CUDART_INF_F, -CUDART_INF_F, -CUDART_INF_F, -CUDART_INF_F);
    for (int i = start + l; i < end; i += 32) {
        int s = g_csr_src[i];
        float4 ss = *(const float4*)(g_ssrc1 + s * 4);
        m.x = fmaxf(m.x, lrelu(ss.x + sd.x));
        m.y = fmaxf(m.y, lrelu(ss.y + sd.y));
        m.z = fmaxf(m.z, lrelu(ss.z + sd.z));
        m.w = fmaxf(m.w, lrelu(ss.w + sd.w));
    }
#pragma unroll
    for (int o = 16; o; o >>= 1) {
        m.x = fmaxf(m.x, __shfl_xor_sync(0xffffffff, m.x, o));
        m.y = fmaxf(m.y, __shfl_xor_sync(0xffffffff, m.y, o));
        m.z = fmaxf(m.z, __shfl_xor_sync(0xffffffff, m.z, o));
        m.w = fmaxf(m.w, __shfl_xor_sync(0xffffffff, m.w, o));
    }

    float a0 = 0.f, a1 = 0.f, a2 = 0.f, a3 = 0.f;
    float4 den = make_float4(0.f, 0.f, 0.f, 0.f);
    for (int base = start; base < end; base += 32) {
        int i = base + l;
        int s_l = 0;
        float4 p_l = make_float4(0.f, 0.f, 0.f, 0.f);
        if (i < end) {
            s_l = g_csr_src[i];
            float4 ss = *(const float4*)(g_ssrc1 + s_l * 4);
            p_l.x = __expf(lrelu(ss.x + sd.x) - m.x);
            p_l.y = __expf(lrelu(ss.y + sd.y) - m.y);
            p_l.z = __expf(lrelu(ss.z + sd.z) - m.z);
            p_l.w = __expf(lrelu(ss.w + sd.w) - m.w);
            den.x += p_l.x; den.y += p_l.y; den.z += p_l.z; den.w += p_l.w;
        }
        int cnt = min(32, end - base);
        for (int j = 0; j < cnt; j++) {
            int   s  = __shfl_sync(0xffffffff, s_l, j);
            float px = __shfl_sync(0xffffffff, p_l.x, j);
            float py = __shfl_sync(0xffffffff, p_l.y, j);
            float pz = __shfl_sync(0xffffffff, p_l.z, j);
            float pw = __shfl_sync(0xffffffff, p_l.w, j);
            const float* hs = g_h1 + (size_t)s * 128;
            a0 = fmaf(px, hs[l],      a0);
            a1 = fmaf(py, hs[32 + l], a1);
            a2 = fmaf(pz, hs[64 + l], a2);
            a3 = fmaf(pw, hs[96 + l], a3);
        }
    }
#pragma unroll
    for (int o = 16; o; o >>= 1) {
        den.x += __shfl_xor_sync(0xffffffff, den.x, o);
        den.y += __shfl_xor_sync(0xffffffff, den.y, o);
        den.z += __shfl_xor_sync(0xffffffff, den.z, o);
        den.w += __shfl_xor_sync(0xffffffff, den.w, o);
    }

    float* od = g_out1 + (size_t)d * 128;
    od[l]      = fmaxf(a0 / den.x + bias[l],      0.f);
    od[32 + l] = fmaxf(a1 / den.y + bias[32 + l], 0.f);
    od[64 + l] = fmaxf(a2 / den.z + bias[64 + l], 0.f);
    od[96 + l] = fmaxf(a3 / den.w + bias[96 + l], 0.f);
}

// ---------------- layer2 GEMM (4 nodes/warp, f32x2) fused with scores ----------------
__global__ void gemm2_kernel(const float* __restrict__ W,
                             const float* __restrict__ a_src,
                             const float* __restrict__ a_dst) {
    __shared__ unsigned long long xs2[32][128];
    int w = threadIdx.x >> 5;
    int l = threadIdx.x & 31;
    int n0 = blockIdx.x * 32 + w * 4;

#pragma unroll
    for (int j = 0; j < 4; j++) {
        int n = n0 + j;
        if (n < NN) {
            float4 v = ((const float4*)(g_out1 + (size_t)n * 128))[l];
            unsigned long long* row = xs2[w * 4 + j] + 4 * l;
            row[0] = pack2(v.x); row[1] = pack2(v.y);
            row[2] = pack2(v.z); row[3] = pack2(v.w);
        }
    }
    __syncwarp();
    if (n0 >= NN) return;

    unsigned long long acc[4] = {};
    const unsigned long long* Wr = (const unsigned long long*)W;  // row k: cols [2l,2l+2)
#pragma unroll 4
    for (int k = 0; k < 128; k++) {
        unsigned long long wv = Wr[k * 32 + l];
#pragma unroll
        for (int j = 0; j < 4; j++) {
            acc[j] = fma2(xs2[w * 4 + j][k], wv, acc[j]);
        }
    }

    float2 as = *(const float2*)(a_src + 2 * l);
    float2 ad = *(const float2*)(a_dst + 2 * l);
#pragma unroll
    for (int j = 0; j < 4; j++) {
        int n = n0 + j;
        if (n >= NN) break;
        ((unsigned long long*)(g_h2 + (size_t)n * 64))[l] = acc[j];
        float ax, ay;
        unpack2(acc[j], ax, ay);
        float ps = ax * as.x + ay * as.y;
        float pd = ax * ad.x + ay * ad.y;
#pragma unroll
        for (int m = 1; m < 32; m <<= 1) {
            ps += __shfl_xor_sync(0xffffffff, ps, m);
            pd += __shfl_xor_sync(0xffffffff, pd, m);
        }
        if (l == 0) {
            g_ssrc2[n] = ps;
            g_sdst2[n] = pd;
        }
    }
}

// ---------------- layer2 fused softmax + aggregation -> output ----------------
__global__ void agg2_kernel(const float* __restrict__ bias, float* __restrict__ out) {
    int w = threadIdx.x >> 5;
    int l = threadIdx.x & 31;
    int d = blockIdx.x * 8 + w;
    if (d >= NN) return;
    int start = g_rowptr[d];
    int end   = g_rowptr[d + 1];
    float sdv = g_sdst2[d];

    float m = -CUDART_INF_F;
    for (int i = start + l; i < end; i += 32) {
        int s = g_csr_src[i];
        m = fmaxf(m, lrelu(g_ssrc2[s] + sdv));
    }
#pragma unroll
    for (int o = 16; o; o >>= 1) m = fmaxf(m, __shfl_xor_sync(0xffffffff, m, o));

    float a0 = 0.f, a1 = 0.f, den = 0.f;
    for (int base = start; base < end; base += 32) {
        int i = base + l;
        int s_l = 0;
        float p_l = 0.f;
        if (i < end) {
            s_l = g_csr_src[i];
            p_l = __expf(lrelu(g_ssrc2[s_l] + sdv) - m);
            den += p_l;
        }
        int cnt = min(32, end - base);
        for (int j = 0; j < cnt; j++) {
            int   s = __shfl_sync(0xffffffff, s_l, j);
            float p = __shfl_sync(0xffffffff, p_l, j);
            const float* hs = g_h2 + (size_t)s * 64;
            a0 = fmaf(p, hs[l],      a0);
            a1 = fmaf(p, hs[32 + l], a1);
        }
    }
#pragma unroll
    for (int o = 16; o; o >>= 1) den += __shfl_xor_sync(0xffffffff, den, o);

    out[(size_t)d * 64 + l]      = a0 / den + bias[l];
    out[(size_t)d * 64 + 32 + l] = a1 / den + bias[32 + l];
}

// ---------------- launch ----------------
extern "C" void kernel_launch(void* const* d_in, const int* in_sizes, int n_in,
                              void* d_out, int out_size) {
    const float* x     = (const float*)d_in[0];
    const void*  ei    = d_in[1];
    const float* W1    = (const float*)d_in[2];
    const float* asrc1 = (const float*)d_in[3];
    const float* adst1 = (const float*)d_in[4];
    const float* b1    = (const float*)d_in[5];
    const float* W2    = (const float*)d_in[6];
    const float* asrc2 = (const float*)d_in[7];
    const float* adst2 = (const float*)d_in[8];
    const float* b2    = (const float*)d_in[9];
    float* out = (float*)d_out;

    const int T = 256;
    detect_dtype<<<1, 128>>>((const unsigned int*)ei);
    zero_cnt<<<(NN + T - 1) / T, T>>>();
    hist_kernel<<<(NT + T - 1) / T, T>>>(ei);
    scan1_kernel<<<NB_SCAN, 1024>>>();
    scan2_kernel<<<1, 64>>>();
    scan3_kernel<<<(NN + T - 1) / T, T>>>();
    scatter_kernel<<<(NT + T - 1) / T, T>>>(ei);
    gemm1_kernel<<<(NN + 31) / 32, 256>>>(x, W1, asrc1, adst1);
    agg1_kernel<<<(NN + 7) / 8, 256>>>(b1);
    gemm2_kernel<<<(NN + 31) / 32, 256>>>(W2, asrc2, adst2);
    agg2_kernel<<<(NN + 7) / 8, 256>>>(b2, out);
}

// round 5
// speedup vs baseline: 2.2803x; 1.1834x over previous
#include <cuda_runtime.h>
#include <cuda_bf16.h>
#include <math_constants.h>

#define NN 50000                 // nodes
#define NE 800000                // raw edges
#define NT (NE + NN)             // edges + self loops
#define NEG_SLOPE 0.2f
#define NB_SCAN ((NN + 1023) / 1024)   // 49 scan blocks

// ---------------- scratch ----------------
__device__ float g_h1[NN * 128];
__device__ float g_ssrc1[NN * 4];
__device__ float g_sdst1[NN * 4];
__device__ float g_out1[NN * 128];
__device__ float g_h2[NN * 64];
__device__ float g_ssrc2[NN];
__device__ float g_sdst2[NN];
__device__ int   g_cnt[NN];
__device__ int   g_rowptr[NN + 1];
__device__ int   g_cursor[NN];
__device__ int   g_csr_src[NT];
__device__ int   g_bsum[64];
__device__ int   g_boff[64];
__device__ int   g_is64;

// ---------------- helpers ----------------
__device__ __forceinline__ float lrelu(float v) { return v > 0.f ? v : NEG_SLOPE * v; }

__device__ __forceinline__ int edge_idx(const void* ei, int row, int e) {
    if (g_is64) return (int)((const long long*)ei)[(size_t)row * NE + e];
    else        return ((const int*)ei)[(size_t)row * NE + e];
}

// packed f32x2 helpers (Blackwell FFMA2 — only via PTX)
__device__ __forceinline__ unsigned long long pack2(float f) {
    unsigned long long r;
    asm("mov.b64 %0, {%1, %1};" : "=l"(r) : "f"(f));
    return r;
}
__device__ __forceinline__ unsigned long long fma2(unsigned long long a,
                                                   unsigned long long b,
                                                   unsigned long long c) {
    unsigned long long d;
    asm("fma.rn.f32x2 %0, %1, %2, %3;" : "=l"(d) : "l"(a), "l"(b), "l"(c));
    return d;
}
__device__ __forceinline__ void unpack2(unsigned long long v, float& lo, float& hi) {
    asm("mov.b64 {%0, %1}, %2;" : "=f"(lo), "=f"(hi) : "l"(v));
}

// ---------------- dtype detection ----------------
__global__ void detect_dtype(const unsigned int* __restrict__ ei_words) {
    __shared__ int any_nonzero;
    if (threadIdx.x == 0) any_nonzero = 0;
    __syncthreads();
    unsigned int w = ei_words[2 * threadIdx.x + 1];
    if (w != 0u) atomicOr(&any_nonzero, 1);
    __syncthreads();
    if (threadIdx.x == 0) g_is64 = any_nonzero ? 0 : 1;
}

// ---------------- CSR build ----------------
__global__ void zero_cnt() {
    int i = blockIdx.x * blockDim.x + threadIdx.x;
    if (i < NN) g_cnt[i] = 0;
}

__global__ void hist_kernel(const void* __restrict__ ei) {
    int e = blockIdx.x * blockDim.x + threadIdx.x;
    if (e >= NT) return;
    int d = (e < NE) ? edge_idx(ei, 1, e) : (e - NE);
    atomicAdd(&g_cnt[d], 1);
}

__global__ void scan1_kernel() {
    __shared__ int wsum[32];
    int t = threadIdx.x;
    int idx = blockIdx.x * 1024 + t;
    int v = (idx < NN) ? g_cnt[idx] : 0;
    int incl = v;
#pragma unroll
    for (int o = 1; o < 32; o <<= 1) {
        int nbr = __shfl_up_sync(0xffffffff, incl, o);
        if ((t & 31) >= o) incl += nbr;
    }
    if ((t & 31) == 31) wsum[t >> 5] = incl;
    __syncthreads();
    if (t < 32) {
        int ws = wsum[t];
        int wincl = ws;
#pragma unroll
        for (int o = 1; o < 32; o <<= 1) {
            int nbr = __shfl_up_sync(0xffffffff, wincl, o);
            if (t >= o) wincl += nbr;
        }
        wsum[t] = wincl - ws;
    }
    __syncthreads();
    int excl = incl - v + wsum[t >> 5];
    if (idx < NN) g_rowptr[idx] = excl;
    if (t == 1023) g_bsum[blockIdx.x] = excl + v;
}

__global__ void scan2_kernel() {
    __shared__ int s[64];
    int t = threadIdx.x;
    int v = (t < NB_SCAN) ? g_bsum[t] : 0;
    s[t] = v;
    __syncthreads();
#pragma unroll
    for (int o = 1; o < 64; o <<= 1) {
        int tmp = (t >= o) ? s[t - o] : 0;
        __syncthreads();
        s[t] += tmp;
        __syncthreads();
    }
    g_boff[t] = s[t] - v;
}

__global__ void scan3_kernel() {
    int idx = blockIdx.x * blockDim.x + threadIdx.x;
    if (idx == 0) g_rowptr[NN] = NT;
    if (idx >= NN) return;
    int r = g_rowptr[idx] + g_boff[idx >> 10];
    g_rowptr[idx] = r;
    g_cursor[idx] = r;
}

__global__ void scatter_kernel(const void* __restrict__ ei) {
    int e = blockIdx.x * blockDim.x + threadIdx.x;
    if (e >= NT) return;
    int s, d;
    if (e < NE) { s = edge_idx(ei, 0, e); d = edge_idx(ei, 1, e); }
    else        { s = e - NE; d = s; }
    int pos = atomicAdd(&g_cursor[d], 1);
    g_csr_src[pos] = s;
}

// ---------------- layer1 GEMM (4 nodes/warp, f32x2) fused with scores ----------------
__global__ void gemm1_kernel(const float* __restrict__ x,
                             const float* __restrict__ W,
                             const float* __restrict__ a_src,
                             const float* __restrict__ a_dst) {
    __shared__ unsigned long long xs2[32][128];
    int w = threadIdx.x >> 5;
    int l = threadIdx.x & 31;
    int n0 = blockIdx.x * 32 + w * 4;

#pragma unroll
    for (int j = 0; j < 4; j++) {
        int n = n0 + j;
        if (n < NN) {
            float4 v = ((const float4*)(x + (size_t)n * 128))[l];
            unsigned long long* row = xs2[w * 4 + j] + 4 * l;
            row[0] = pack2(v.x); row[1] = pack2(v.y);
            row[2] = pack2(v.z); row[3] = pack2(v.w);
        }
    }
    __syncwarp();
    if (n0 >= NN) return;

    unsigned long long acc01[4] = {}, acc23[4] = {};
    const ulonglong2* Wr = (const ulonglong2*)W;
#pragma unroll 4
    for (int k = 0; k < 128; k++) {
        ulonglong2 wv = Wr[k * 32 + l];
#pragma unroll
        for (int j = 0; j < 4; j++) {
            unsigned long long xv = xs2[w * 4 + j][k];
            acc01[j] = fma2(xv, wv.x, acc01[j]);
            acc23[j] = fma2(xv, wv.y, acc23[j]);
        }
    }

    int h   = l >> 3;
    int off = (l & 7) * 4;
    float4 as = *(const float4*)(a_src + h * 32 + off);
    float4 ad = *(const float4*)(a_dst + h * 32 + off);

#pragma unroll
    for (int j = 0; j < 4; j++) {
        int n = n0 + j;
        if (n >= NN) break;
        ulonglong2 st; st.x = acc01[j]; st.y = acc23[j];
        ((ulonglong2*)(g_h1 + (size_t)n * 128))[l] = st;
        float ax, ay, az, aw;
        unpack2(acc01[j], ax, ay);
        unpack2(acc23[j], az, aw);
        float ps = ax * as.x + ay * as.y + az * as.z + aw * as.w;
        float pd = ax * ad.x + ay * ad.y + az * ad.z + aw * ad.w;
#pragma unroll
        for (int m = 1; m < 8; m <<= 1) {
            ps += __shfl_xor_sync(0xffffffff, ps, m);
            pd += __shfl_xor_sync(0xffffffff, pd, m);
        }
        if ((l & 7) == 0) {
            g_ssrc1[n * 4 + h] = ps;
            g_sdst1[n * 4 + h] = pd;
        }
    }
}

// ---------------- layer1 fused softmax + aggregation (warp per node) ----------------
// lane l owns output channels [4l, 4l+4): one LDG.128 per edge, SMEM broadcast of (s, p).
__global__ void agg1_kernel(const float* __restrict__ bias) {
    __shared__ int   sh_s[8][32];
    __shared__ float sh_p[8][4][32];
    int w = threadIdx.x >> 5;
    int l = threadIdx.x & 31;
    int d = blockIdx.x * 8 + w;
    if (d >= NN) return;
    int start = g_rowptr[d];
    int end   = g_rowptr[d + 1];
    float4 sd = *(const float4*)(g_sdst1 + d * 4);
    int h = l >> 3;   // head owning this lane's channels

    // phase A: segment max per head
    float4 m = make_float4(-CUDART_INF_F, -CUDART_INF_F, -CUDART_INF_F, -CUDART_INF_F);
    for (int i = start + l; i < end; i += 32) {
        int s = g_csr_src[i];
        float4 ss = *(const float4*)(g_ssrc1 + s * 4);
        m.x = fmaxf(m.x, lrelu(ss.x + sd.x));
        m.y = fmaxf(m.y, lrelu(ss.y + sd.y));
        m.z = fmaxf(m.z, lrelu(ss.z + sd.z));
        m.w = fmaxf(m.w, lrelu(ss.w + sd.w));
    }
#pragma unroll
    for (int o = 16; o; o >>= 1) {
        m.x = fmaxf(m.x, __shfl_xor_sync(0xffffffff, m.x, o));
        m.y = fmaxf(m.y, __shfl_xor_sync(0xffffffff, m.y, o));
        m.z = fmaxf(m.z, __shfl_xor_sync(0xffffffff, m.z, o));
        m.w = fmaxf(m.w, __shfl_xor_sync(0xffffffff, m.w, o));
    }

    // phase B
    unsigned long long acc01 = 0ull, acc23 = 0ull;   // channels 4l,4l+1 | 4l+2,4l+3
    float4 den = make_float4(0.f, 0.f, 0.f, 0.f);
    for (int base = start; base < end; base += 32) {
        int i = base + l;
        int s_l = 0;
        float4 p_l = make_float4(0.f, 0.f, 0.f, 0.f);
        if (i < end) {
            s_l = g_csr_src[i];
            float4 ss = *(const float4*)(g_ssrc1 + s_l * 4);
            p_l.x = __expf(lrelu(ss.x + sd.x) - m.x);
            p_l.y = __expf(lrelu(ss.y + sd.y) - m.y);
            p_l.z = __expf(lrelu(ss.z + sd.z) - m.z);
            p_l.w = __expf(lrelu(ss.w + sd.w) - m.w);
            den.x += p_l.x; den.y += p_l.y; den.z += p_l.z; den.w += p_l.w;
        }
        sh_s[w][l] = s_l;
        sh_p[w][0][l] = p_l.x;
        sh_p[w][1][l] = p_l.y;
        sh_p[w][2][l] = p_l.z;
        sh_p[w][3][l] = p_l.w;
        __syncwarp();
        int cnt = min(32, end - base);
        for (int j = 0; j < cnt; j++) {
            int   s  = sh_s[w][j];
            float ph = sh_p[w][h][j];
            ulonglong2 hv = *(const ulonglong2*)(g_h1 + (size_t)s * 128 + 4 * l);
            unsigned long long p2 = pack2(ph);
            acc01 = fma2(p2, hv.x, acc01);
            acc23 = fma2(p2, hv.y, acc23);
        }
        __syncwarp();
    }
#pragma unroll
    for (int o = 16; o; o >>= 1) {
        den.x += __shfl_xor_sync(0xffffffff, den.x, o);
        den.y += __shfl_xor_sync(0xffffffff, den.y, o);
        den.z += __shfl_xor_sync(0xffffffff, den.z, o);
        den.w += __shfl_xor_sync(0xffffffff, den.w, o);
    }
    float denh = (h == 0) ? den.x : (h == 1) ? den.y : (h == 2) ? den.z : den.w;

    float a0, a1, a2, a3;
    unpack2(acc01, a0, a1);
    unpack2(acc23, a2, a3);
    float4 bv = *(const float4*)(bias + 4 * l);
    float4 o;
    o.x = fmaxf(a0 / denh + bv.x, 0.f);
    o.y = fmaxf(a1 / denh + bv.y, 0.f);
    o.z = fmaxf(a2 / denh + bv.z, 0.f);
    o.w = fmaxf(a3 / denh + bv.w, 0.f);
    ((float4*)(g_out1 + (size_t)d * 128))[l] = o;
}

// ---------------- layer2 GEMM (4 nodes/warp, f32x2) fused with scores ----------------
__global__ void gemm2_kernel(const float* __restrict__ W,
                             const float* __restrict__ a_src,
                             const float* __restrict__ a_dst) {
    __shared__ unsigned long long xs2[32][128];
    int w = threadIdx.x >> 5;
    int l = threadIdx.x & 31;
    int n0 = blockIdx.x * 32 + w * 4;

#pragma unroll
    for (int j = 0; j < 4; j++) {
        int n = n0 + j;
        if (n < NN) {
            float4 v = ((const float4*)(g_out1 + (size_t)n * 128))[l];
            unsigned long long* row = xs2[w * 4 + j] + 4 * l;
            row[0] = pack2(v.x); row[1] = pack2(v.y);
            row[2] = pack2(v.z); row[3] = pack2(v.w);
        }
    }
    __syncwarp();
    if (n0 >= NN) return;

    unsigned long long acc[4] = {};
    const unsigned long long* Wr = (const unsigned long long*)W;
#pragma unroll 4
    for (int k = 0; k < 128; k++) {
        unsigned long long wv = Wr[k * 32 + l];
#pragma unroll
        for (int j = 0; j < 4; j++) {
            acc[j] = fma2(xs2[w * 4 + j][k], wv, acc[j]);
        }
    }

    float2 as = *(const float2*)(a_src + 2 * l);
    float2 ad = *(const float2*)(a_dst + 2 * l);
#pragma unroll
    for (int j = 0; j < 4; j++) {
        int n = n0 + j;
        if (n >= NN) break;
        ((unsigned long long*)(g_h2 + (size_t)n * 64))[l] = acc[j];
        float ax, ay;
        unpack2(acc[j], ax, ay);
        float ps = ax * as.x + ay * as.y;
        float pd = ax * ad.x + ay * ad.y;
#pragma unroll
        for (int m = 1; m < 32; m <<= 1) {
            ps += __shfl_xor_sync(0xffffffff, ps, m);
            pd += __shfl_xor_sync(0xffffffff, pd, m);
        }
        if (l == 0) {
            g_ssrc2[n] = ps;
            g_sdst2[n] = pd;
        }
    }
}

// ---------------- layer2 fused softmax + aggregation -> output ----------------
// lane l owns output channels 2l, 2l+1: one LDG.64 per edge, SMEM broadcast.
__global__ void agg2_kernel(const float* __restrict__ bias, float* __restrict__ out) {
    __shared__ int   sh_s[8][32];
    __shared__ float sh_p[8][32];
    int w = threadIdx.x >> 5;
    int l = threadIdx.x & 31;
    int d = blockIdx.x * 8 + w;
    if (d >= NN) return;
    int start = g_rowptr[d];
    int end   = g_rowptr[d + 1];
    float sdv = g_sdst2[d];

    float m = -CUDART_INF_F;
    for (int i = start + l; i < end; i += 32) {
        int s = g_csr_src[i];
        m = fmaxf(m, lrelu(g_ssrc2[s] + sdv));
    }
#pragma unroll
    for (int o = 16; o; o >>= 1) m = fmaxf(m, __shfl_xor_sync(0xffffffff, m, o));

    unsigned long long acc = 0ull;
    float den = 0.f;
    for (int base = start; base < end; base += 32) {
        int i = base + l;
        int s_l = 0;
        float p_l = 0.f;
        if (i < end) {
            s_l = g_csr_src[i];
            p_l = __expf(lrelu(g_ssrc2[s_l] + sdv) - m);
            den += p_l;
        }
        sh_s[w][l] = s_l;
        sh_p[w][l] = p_l;
        __syncwarp();
        int cnt = min(32, end - base);
        for (int j = 0; j < cnt; j++) {
            int   s = sh_s[w][j];
            float p = sh_p[w][j];
            unsigned long long hv = *(const unsigned long long*)(g_h2 + (size_t)s * 64 + 2 * l);
            acc = fma2(pack2(p), hv, acc);
        }
        __syncwarp();
    }
#pragma unroll
    for (int o = 16; o; o >>= 1) den += __shfl_xor_sync(0xffffffff, den, o);

    float a0, a1;
    unpack2(acc, a0, a1);
    float2 bv = *(const float2*)(bias + 2 * l);
    float2 o2;
    o2.x = a0 / den + bv.x;
    o2.y = a1 / den + bv.y;
    *(float2*)(out + (size_t)d * 64 + 2 * l) = o2;
}

// ---------------- launch ----------------
extern "C" void kernel_launch(void* const* d_in, const int* in_sizes, int n_in,
                              void* d_out, int out_size) {
    const float* x     = (const float*)d_in[0];
    const void*  ei    = d_in[1];
    const float* W1    = (const float*)d_in[2];
    const float* asrc1 = (const float*)d_in[3];
    const float* adst1 = (const float*)d_in[4];
    const float* b1    = (const float*)d_in[5];
    const float* W2    = (const float*)d_in[6];
    const float* asrc2 = (const float*)d_in[7];
    const float* adst2 = (const float*)d_in[8];
    const float* b2    = (const float*)d_in[9];
    float* out = (float*)d_out;

    const int T = 256;
    detect_dtype<<<1, 128>>>((const unsigned int*)ei);
    zero_cnt<<<(NN + T - 1) / T, T>>>();
    hist_kernel<<<(NT + T - 1) / T, T>>>(ei);
    gemm1_kernel<<<(NN + 31) / 32, 256>>>(x, W1, asrc1, adst1);   // 4th launch -> profiled
    scan1_kernel<<<NB_SCAN, 1024>>>();
    scan2_kernel<<<1, 64>>>();
    scan3_kernel<<<(NN + T - 1) / T, T>>>();
    scatter_kernel<<<(NT + T - 1) / T, T>>>(ei);
    agg1_kernel<<<(NN + 7) / 8, 256>>>(b1);
    gemm2_kernel<<<(NN + 31) / 32, 256>>>(W2, asrc2, adst2);
    agg2_kernel<<<(NN + 7) / 8, 256>>>(b2, out);
}

// round 7
// speedup vs baseline: 2.3209x; 1.0178x over previous
#include <cuda_runtime.h>
#include <cuda_bf16.h>
#include <math_constants.h>

#define NN 50000                 // nodes
#define NE 800000                // raw edges
#define NT (NE + NN)             // edges + self loops
#define NEG_SLOPE 0.2f
#define NB_SCAN ((NN + 1023) / 1024)   // 49 scan blocks

// ---------------- scratch ----------------
__device__ float g_h1[NN * 128];
__device__ float g_ssrc1[NN * 4];
__device__ float g_sdst1[NN * 4];
__device__ float g_out1[NN * 128];
__device__ float g_h2[NN * 64];
__device__ float g_ssrc2[NN];
__device__ float g_sdst2[NN];
__device__ int   g_cnt[NN];
__device__ int   g_rowptr[NN + 1];
__device__ int   g_cursor[NN];
__device__ int   g_csr_src[NT];
__device__ int   g_bsum[64];
__device__ int   g_boff[64];
__device__ int   g_is64;

// ---------------- helpers ----------------
__device__ __forceinline__ float lrelu(float v) { return v > 0.f ? v : NEG_SLOPE * v; }

__device__ __forceinline__ int edge_idx(const void* ei, int row, int e) {
    if (g_is64) return (int)((const long long*)ei)[(size_t)row * NE + e];
    else        return ((const int*)ei)[(size_t)row * NE + e];
}

// packed f32x2 helpers (Blackwell FFMA2 — only via PTX)
__device__ __forceinline__ unsigned long long pack2(float f) {
    unsigned long long r;
    asm("mov.b64 %0, {%1, %1};" : "=l"(r) : "f"(f));
    return r;
}
__device__ __forceinline__ unsigned long long fma2(unsigned long long a,
                                                   unsigned long long b,
                                                   unsigned long long c) {
    unsigned long long d;
    asm("fma.rn.f32x2 %0, %1, %2, %3;" : "=l"(d) : "l"(a), "l"(b), "l"(c));
    return d;
}
__device__ __forceinline__ void unpack2(unsigned long long v, float& lo, float& hi) {
    asm("mov.b64 {%0, %1}, %2;" : "=f"(lo), "=f"(hi) : "l"(v));
}

// ---------------- dtype detection ----------------
__global__ void detect_dtype(const unsigned int* __restrict__ ei_words) {
    __shared__ int any_nonzero;
    if (threadIdx.x == 0) any_nonzero = 0;
    __syncthreads();
    unsigned int w = ei_words[2 * threadIdx.x + 1];
    if (w != 0u) atomicOr(&any_nonzero, 1);
    __syncthreads();
    if (threadIdx.x == 0) g_is64 = any_nonzero ? 0 : 1;
}

// ---------------- CSR build ----------------
__global__ void zero_cnt() {
    int i = blockIdx.x * blockDim.x + threadIdx.x;
    if (i < NN) g_cnt[i] = 0;
}

__global__ void hist_kernel(const void* __restrict__ ei) {
    int e = blockIdx.x * blockDim.x + threadIdx.x;
    if (e >= NT) return;
    int d = (e < NE) ? edge_idx(ei, 1, e) : (e - NE);
    atomicAdd(&g_cnt[d], 1);
}

__global__ void scan1_kernel() {
    __shared__ int wsum[32];
    int t = threadIdx.x;
    int idx = blockIdx.x * 1024 + t;
    int v = (idx < NN) ? g_cnt[idx] : 0;
    int incl = v;
#pragma unroll
    for (int o = 1; o < 32; o <<= 1) {
        int nbr = __shfl_up_sync(0xffffffff, incl, o);
        if ((t & 31) >= o) incl += nbr;
    }
    if ((t & 31) == 31) wsum[t >> 5] = incl;
    __syncthreads();
    if (t < 32) {
        int ws = wsum[t];
        int wincl = ws;
#pragma unroll
        for (int o = 1; o < 32; o <<= 1) {
            int nbr = __shfl_up_sync(0xffffffff, wincl, o);
            if (t >= o) wincl += nbr;
        }
        wsum[t] = wincl - ws;
    }
    __syncthreads();
    int excl = incl - v + wsum[t >> 5];
    if (idx < NN) g_rowptr[idx] = excl;
    if (t == 1023) g_bsum[blockIdx.x] = excl + v;
}

__global__ void scan2_kernel() {
    __shared__ int s[64];
    int t = threadIdx.x;
    int v = (t < NB_SCAN) ? g_bsum[t] : 0;
    s[t] = v;
    __syncthreads();
#pragma unroll
    for (int o = 1; o < 64; o <<= 1) {
        int tmp = (t >= o) ? s[t - o] : 0;
        __syncthreads();
        s[t] += tmp;
        __syncthreads();
    }
    g_boff[t] = s[t] - v;
}

__global__ void scan3_kernel() {
    int idx = blockIdx.x * blockDim.x + threadIdx.x;
    if (idx == 0) g_rowptr[NN] = NT;
    if (idx >= NN) return;
    int r = g_rowptr[idx] + g_boff[idx >> 10];
    g_rowptr[idx] = r;
    g_cursor[idx] = r;
}

__global__ void scatter_kernel(const void* __restrict__ ei) {
    int e = blockIdx.x * blockDim.x + threadIdx.x;
    if (e >= NT) return;
    int s, d;
    if (e < NE) { s = edge_idx(ei, 0, e); d = edge_idx(ei, 1, e); }
    else        { s = e - NE; d = s; }
    int pos = atomicAdd(&g_cursor[d], 1);
    g_csr_src[pos] = s;
}

// ---------------- layer1 GEMM: 64-node x 128-col block tile, 4x8 register tiles ----------------
// thread (tx = t&15, ty = t>>4): nodes nbase+ty*4..+3, cols tx*8..tx*8+7.
__global__ void __launch_bounds__(256, 2) gemm1_kernel(const float* __restrict__ x,
                             const float* __restrict__ W,
                             const float* __restrict__ a_src,
                             const float* __restrict__ a_dst) {
    __shared__ float xs[64][128];     // 32KB
    int t = threadIdx.x;
    int tx = t & 15, ty = t >> 4;
    int nbase = blockIdx.x * 64;

    for (int i = t; i < 64 * 32; i += 256) {
        int n = i >> 5, kc = i & 31;
        int node = nbase + n;
        float4 v = (node < NN) ? ((const float4*)(x + (size_t)node * 128))[kc]
                               : make_float4(0.f, 0.f, 0.f, 0.f);
        ((float4*)xs[n])[kc] = v;
    }
    __syncthreads();

    unsigned long long acc[4][4] = {};   // [node j][col-pair p] -> cols tx*8+2p, +1
    const ulonglong2* Wp = (const ulonglong2*)W;   // ulonglong2 = 4 floats; row k col c -> (k*128+c)/4
#pragma unroll 4
    for (int k = 0; k < 128; k++) {
        ulonglong2 w01 = Wp[k * 32 + tx * 2];       // cols tx*8 .. +3
        ulonglong2 w23 = Wp[k * 32 + tx * 2 + 1];   // cols tx*8+4 .. +7
#pragma unroll
        for (int j = 0; j < 4; j++) {
            unsigned long long xp = pack2(xs[ty * 4 + j][k]);
            acc[j][0] = fma2(xp, w01.x, acc[j][0]);
            acc[j][1] = fma2(xp, w01.y, acc[j][1]);
            acc[j][2] = fma2(xp, w23.x, acc[j][2]);
            acc[j][3] = fma2(xp, w23.y, acc[j][3]);
        }
    }

    int h  = tx >> 2;            // head owning cols tx*8..
    int co = (tx & 3) * 8;       // offset within head
    float4 as0 = *(const float4*)(a_src + h * 32 + co);
    float4 as1 = *(const float4*)(a_src + h * 32 + co + 4);
    float4 ad0 = *(const float4*)(a_dst + h * 32 + co);
    float4 ad1 = *(const float4*)(a_dst + h * 32 + co + 4);

#pragma unroll
    for (int j = 0; j < 4; j++) {
        int node = nbase + ty * 4 + j;
        float f0, f1, f2, f3, f4, f5, f6, f7;
        unpack2(acc[j][0], f0, f1);
        unpack2(acc[j][1], f2, f3);
        unpack2(acc[j][2], f4, f5);
        unpack2(acc[j][3], f6, f7);
        if (node < NN) {
            ulonglong2* hp = (ulonglong2*)(g_h1 + (size_t)node * 128 + tx * 8);
            hp[0] = make_ulonglong2(acc[j][0], acc[j][1]);
            hp[1] = make_ulonglong2(acc[j][2], acc[j][3]);
        }
        float ps = f0 * as0.x + f1 * as0.y + f2 * as0.z + f3 * as0.w
                 + f4 * as1.x + f5 * as1.y + f6 * as1.z + f7 * as1.w;
        float pd = f0 * ad0.x + f1 * ad0.y + f2 * ad0.z + f3 * ad0.w
                 + f4 * ad1.x + f5 * ad1.y + f6 * ad1.z + f7 * ad1.w;
        ps += __shfl_xor_sync(0xffffffff, ps, 1);
        ps += __shfl_xor_sync(0xffffffff, ps, 2);
        pd += __shfl_xor_sync(0xffffffff, pd, 1);
        pd += __shfl_xor_sync(0xffffffff, pd, 2);
        if ((tx & 3) == 0 && node < NN) {
            g_ssrc1[node * 4 + h] = ps;
            g_sdst1[node * 4 + h] = pd;
        }
    }
}

// ---------------- layer1 fused softmax + aggregation (warp per node) ----------------
__global__ void agg1_kernel(const float* __restrict__ bias) {
    __shared__ int   sh_s[8][32];
    __shared__ float sh_p[8][4][32];
    int w = threadIdx.x >> 5;
    int l = threadIdx.x & 31;
    int d = blockIdx.x * 8 + w;
    if (d >= NN) return;
    int start = g_rowptr[d];
    int end   = g_rowptr[d + 1];
    float4 sd = *(const float4*)(g_sdst1 + d * 4);
    int h = l >> 3;

    float4 m = make_float4(-CUDART_INF_F, -CUDART_INF_F, -CUDART_INF_F, -CUDART_INF_F);
    for (int i = start + l; i < end; i += 32) {
        int s = g_csr_src[i];
        float4 ss = *(const float4*)(g_ssrc1 + s * 4);
        m.x = fmaxf(m.x, lrelu(ss.x + sd.x));
        m.y = fmaxf(m.y, lrelu(ss.y + sd.y));
        m.z = fmaxf(m.z, lrelu(ss.z + sd.z));
        m.w = fmaxf(m.w, lrelu(ss.w + sd.w));
    }
#pragma unroll
    for (int o = 16; o; o >>= 1) {
        m.x = fmaxf(m.x, __shfl_xor_sync(0xffffffff, m.x, o));
        m.y = fmaxf(m.y, __shfl_xor_sync(0xffffffff, m.y, o));
        m.z = fmaxf(m.z, __shfl_xor_sync(0xffffffff, m.z, o));
        m.w = fmaxf(m.w, __shfl_xor_sync(0xffffffff, m.w, o));
    }

    unsigned long long acc01 = 0ull, acc23 = 0ull;
    float4 den = make_float4(0.f, 0.f, 0.f, 0.f);
    for (int base = start; base < end; base += 32) {
        int i = base + l;
        int s_l = 0;
        float4 p_l = make_float4(0.f, 0.f, 0.f, 0.f);
        if (i < end) {
            s_l = g_csr_src[i];
            float4 ss = *(const float4*)(g_ssrc1 + s_l * 4);
            p_l.x = __expf(lrelu(ss.x + sd.x) - m.x);
            p_l.y = __expf(lrelu(ss.y + sd.y) - m.y);
            p_l.z = __expf(lrelu(ss.z + sd.z) - m.z);
            p_l.w = __expf(lrelu(ss.w + sd.w) - m.w);
            den.x += p_l.x; den.y += p_l.y; den.z += p_l.z; den.w += p_l.w;
        }
        sh_s[w][l] = s_l;
        sh_p[w][0][l] = p_l.x;
        sh_p[w][1][l] = p_l.y;
        sh_p[w][2][l] = p_l.z;
        sh_p[w][3][l] = p_l.w;
        __syncwarp();
        int cnt = min(32, end - base);
        for (int j = 0; j < cnt; j++) {
            int   s  = sh_s[w][j];
            float ph = sh_p[w][h][j];
            ulonglong2 hv = *(const ulonglong2*)(g_h1 + (size_t)s * 128 + 4 * l);
            unsigned long long p2 = pack2(ph);
            acc01 = fma2(p2, hv.x, acc01);
            acc23 = fma2(p2, hv.y, acc23);
        }
        __syncwarp();
    }
#pragma unroll
    for (int o = 16; o; o >>= 1) {
        den.x += __shfl_xor_sync(0xffffffff, den.x, o);
        den.y += __shfl_xor_sync(0xffffffff, den.y, o);
        den.z += __shfl_xor_sync(0xffffffff, den.z, o);
        den.w += __shfl_xor_sync(0xffffffff, den.w, o);
    }
    float denh = (h == 0) ? den.x : (h == 1) ? den.y : (h == 2) ? den.z : den.w;

    float a0, a1, a2, a3;
    unpack2(acc01, a0, a1);
    unpack2(acc23, a2, a3);
    float4 bv = *(const float4*)(bias + 4 * l);
    float4 o;
    o.x = fmaxf(a0 / denh + bv.x, 0.f);
    o.y = fmaxf(a1 / denh + bv.y, 0.f);
    o.z = fmaxf(a2 / denh + bv.z, 0.f);
    o.w = fmaxf(a3 / denh + bv.w, 0.f);
    ((float4*)(g_out1 + (size_t)d * 128))[l] = o;
}

// ---------------- layer2 GEMM: 64-node x 64-col block tile, 4x4 register tiles ----------------
__global__ void __launch_bounds__(256, 2) gemm2_kernel(const float* __restrict__ W,
                             const float* __restrict__ a_src,
                             const float* __restrict__ a_dst) {
    __shared__ float xs[64][128];
    int t = threadIdx.x;
    int tx = t & 15, ty = t >> 4;
    int nbase = blockIdx.x * 64;

    for (int i = t; i < 64 * 32; i += 256) {
        int n = i >> 5, kc = i & 31;
        int node = nbase + n;
        float4 v = (node < NN) ? ((const float4*)(g_out1 + (size_t)node * 128))[kc]
                               : make_float4(0.f, 0.f, 0.f, 0.f);
        ((float4*)xs[n])[kc] = v;
    }
    __syncthreads();

    unsigned long long acc[4][2] = {};   // [node j][pair p] -> cols tx*4+2p, +1
    const ulonglong2* Wp = (const ulonglong2*)W;   // row k col c -> (k*64+c)/4
#pragma unroll 4
    for (int k = 0; k < 128; k++) {
        ulonglong2 wv = Wp[k * 16 + tx];   // cols tx*4 .. +3
#pragma unroll
        for (int j = 0; j < 4; j++) {
            unsigned long long xp = pack2(xs[ty * 4 + j][k]);
            acc[j][0] = fma2(xp, wv.x, acc[j][0]);
            acc[j][1] = fma2(xp, wv.y, acc[j][1]);
        }
    }

    float4 as = *(const float4*)(a_src + tx * 4);
    float4 ad = *(const float4*)(a_dst + tx * 4);
#pragma unroll
    for (int j = 0; j < 4; j++) {
        int node = nbase + ty * 4 + j;
        float f0, f1, f2, f3;
        unpack2(acc[j][0], f0, f1);
        unpack2(acc[j][1], f2, f3);
        if (node < NN) {
            *(ulonglong2*)(g_h2 + (size_t)node * 64 + tx * 4) =
                make_ulonglong2(acc[j][0], acc[j][1]);
        }
        float ps = f0 * as.x + f1 * as.y + f2 * as.z + f3 * as.w;
        float pd = f0 * ad.x + f1 * ad.y + f2 * ad.z + f3 * ad.w;
#pragma unroll
        for (int o = 1; o < 16; o <<= 1) {
            ps += __shfl_xor_sync(0xffffffff, ps, o);
            pd += __shfl_xor_sync(0xffffffff, pd, o);
        }
        if (tx == 0 && node < NN) {
            g_ssrc2[node] = ps;
            g_sdst2[node] = pd;
        }
    }
}

// ---------------- layer2 fused softmax + aggregation -> output ----------------
__global__ void agg2_kernel(const float* __restrict__ bias, float* __restrict__ out) {
    __shared__ int   sh_s[8][32];
    __shared__ float sh_p[8][32];
    int w = threadIdx.x >> 5;
    int l = threadIdx.x & 31;
    int d = blockIdx.x * 8 + w;
    if (d >= NN) return;
    int start = g_rowptr[d];
    int end   = g_rowptr[d + 1];
    float sdv = g_sdst2[d];

    float m = -CUDART_INF_F;
    for (int i = start + l; i < end; i += 32) {
        int s = g_csr_src[i];
        m = fmaxf(m, lrelu(g_ssrc2[s] + sdv));
    }
#pragma unroll
    for (int o = 16; o; o >>= 1) m = fmaxf(m, __shfl_xor_sync(0xffffffff, m, o));

    unsigned long long acc = 0ull;
    float den = 0.f;
    for (int base = start; base < end; base += 32) {
        int i = base + l;
        int s_l = 0;
        float p_l = 0.f;
        if (i < end) {
            s_l = g_csr_src[i];
            p_l = __expf(lrelu(g_ssrc2[s_l] + sdv) - m);
            den += p_l;
        }
        sh_s[w][l] = s_l;
        sh_p[w][l] = p_l;
        __syncwarp();
        int cnt = min(32, end - base);
        for (int j = 0; j < cnt; j++) {
            int   s = sh_s[w][j];
            float p = sh_p[w][j];
            unsigned long long hv = *(const unsigned long long*)(g_h2 + (size_t)s * 64 + 2 * l);
            acc = fma2(pack2(p), hv, acc);
        }
        __syncwarp();
    }
#pragma unroll
    for (int o = 16; o; o >>= 1) den += __shfl_xor_sync(0xffffffff, den, o);

    float a0, a1;
    unpack2(acc, a0, a1);
    float2 bv = *(const float2*)(bias + 2 * l);
    float2 o2;
    o2.x = a0 / den + bv.x;
    o2.y = a1 / den + bv.y;
    *(float2*)(out + (size_t)d * 64 + 2 * l) = o2;
}

// ---------------- launch ----------------
extern "C" void kernel_launch(void* const* d_in, const int* in_sizes, int n_in,
                              void* d_out, int out_size) {
    const float* x     = (const float*)d_in[0];
    const void*  ei    = d_in[1];
    const float* W1    = (const float*)d_in[2];
    const float* asrc1 = (const float*)d_in[3];
    const float* adst1 = (const float*)d_in[4];
    const float* b1    = (const float*)d_in[5];
    const float* W2    = (const float*)d_in[6];
    const float* asrc2 = (const float*)d_in[7];
    const float* adst2 = (const float*)d_in[8];
    const float* b2    = (const float*)d_in[9];
    float* out = (float*)d_out;

    const int T = 256;
    const int NBG = (NN + 63) / 64;
    detect_dtype<<<1, 128>>>((const unsigned int*)ei);
    zero_cnt<<<(NN + T - 1) / T, T>>>();
    hist_kernel<<<(NT + T - 1) / T, T>>>(ei);
    gemm1_kernel<<<NBG, 256>>>(x, W1, asrc1, adst1);   // 4th launch -> profiled
    scan1_kernel<<<NB_SCAN, 1024>>>();
    scan2_kernel<<<1, 64>>>();
    scan3_kernel<<<(NN + T - 1) / T, T>>>();
    scatter_kernel<<<(NT + T - 1) / T, T>>>(ei);
    agg1_kernel<<<(NN + 7) / 8, 256>>>(b1);
    gemm2_kernel<<<NBG, 256>>>(W2, asrc2, adst2);
    agg2_kernel<<<(NN + 7) / 8, 256>>>(b2, out);
}

// round 8
// speedup vs baseline: 2.3275x; 1.0028x over previous
#include <cuda_runtime.h>
#include <cuda_bf16.h>
#include <math_constants.h>

#define NN 50000                 // nodes
#define NE 800000                // raw edges
#define NT (NE + NN)             // edges + self loops
#define NEG_SLOPE 0.2f
#define NB_SCAN ((NN + 1023) / 1024)   // 49 scan blocks
#define XPAD 140                 // padded shared row stride (floats): 4-row diff -> bank+16, 16B aligned

// ---------------- scratch ----------------
__device__ float g_h1[NN * 128];
__device__ float g_ssrc1[NN * 4];
__device__ float g_sdst1[NN * 4];
__device__ float g_out1[NN * 128];
__device__ float g_h2[NN * 64];
__device__ float g_ssrc2[NN];
__device__ float g_sdst2[NN];
__device__ int   g_cnt[NN];
__device__ int   g_rowptr[NN + 1];
__device__ int   g_cursor[NN];
__device__ int   g_csr_src[NT];
__device__ int   g_bsum[64];
__device__ int   g_boff[64];
__device__ int   g_is64;

// ---------------- helpers ----------------
__device__ __forceinline__ float lrelu(float v) { return v > 0.f ? v : NEG_SLOPE * v; }

__device__ __forceinline__ int edge_idx(const void* ei, int row, int e) {
    if (g_is64) return (int)((const long long*)ei)[(size_t)row * NE + e];
    else        return ((const int*)ei)[(size_t)row * NE + e];
}

// packed f32x2 helpers (Blackwell FFMA2 — only via PTX)
__device__ __forceinline__ unsigned long long pack2(float f) {
    unsigned long long r;
    asm("mov.b64 %0, {%1, %1};" : "=l"(r) : "f"(f));
    return r;
}
__device__ __forceinline__ unsigned long long fma2(unsigned long long a,
                                                   unsigned long long b,
                                                   unsigned long long c) {
    unsigned long long d;
    asm("fma.rn.f32x2 %0, %1, %2, %3;" : "=l"(d) : "l"(a), "l"(b), "l"(c));
    return d;
}
__device__ __forceinline__ void unpack2(unsigned long long v, float& lo, float& hi) {
    asm("mov.b64 {%0, %1}, %2;" : "=f"(lo), "=f"(hi) : "l"(v));
}

// ---------------- dtype detection ----------------
__global__ void detect_dtype(const unsigned int* __restrict__ ei_words) {
    __shared__ int any_nonzero;
    if (threadIdx.x == 0) any_nonzero = 0;
    __syncthreads();
    unsigned int w = ei_words[2 * threadIdx.x + 1];
    if (w != 0u) atomicOr(&any_nonzero, 1);
    __syncthreads();
    if (threadIdx.x == 0) g_is64 = any_nonzero ? 0 : 1;
}

// ---------------- CSR build ----------------
__global__ void zero_cnt() {
    int i = blockIdx.x * blockDim.x + threadIdx.x;
    if (i < NN) g_cnt[i] = 0;
}

__global__ void hist_kernel(const void* __restrict__ ei) {
    int e = blockIdx.x * blockDim.x + threadIdx.x;
    if (e >= NT) return;
    int d = (e < NE) ? edge_idx(ei, 1, e) : (e - NE);
    atomicAdd(&g_cnt[d], 1);
}

__global__ void scan1_kernel() {
    __shared__ int wsum[32];
    int t = threadIdx.x;
    int idx = blockIdx.x * 1024 + t;
    int v = (idx < NN) ? g_cnt[idx] : 0;
    int incl = v;
#pragma unroll
    for (int o = 1; o < 32; o <<= 1) {
        int nbr = __shfl_up_sync(0xffffffff, incl, o);
        if ((t & 31) >= o) incl += nbr;
    }
    if ((t & 31) == 31) wsum[t >> 5] = incl;
    __syncthreads();
    if (t < 32) {
        int ws = wsum[t];
        int wincl = ws;
#pragma unroll
        for (int o = 1; o < 32; o <<= 1) {
            int nbr = __shfl_up_sync(0xffffffff, wincl, o);
            if (t >= o) wincl += nbr;
        }
        wsum[t] = wincl - ws;
    }
    __syncthreads();
    int excl = incl - v + wsum[t >> 5];
    if (idx < NN) g_rowptr[idx] = excl;
    if (t == 1023) g_bsum[blockIdx.x] = excl + v;
}

__global__ void scan2_kernel() {
    __shared__ int s[64];
    int t = threadIdx.x;
    int v = (t < NB_SCAN) ? g_bsum[t] : 0;
    s[t] = v;
    __syncthreads();
#pragma unroll
    for (int o = 1; o < 64; o <<= 1) {
        int tmp = (t >= o) ? s[t - o] : 0;
        __syncthreads();
        s[t] += tmp;
        __syncthreads();
    }
    g_boff[t] = s[t] - v;
}

__global__ void scan3_kernel() {
    int idx = blockIdx.x * blockDim.x + threadIdx.x;
    if (idx == 0) g_rowptr[NN] = NT;
    if (idx >= NN) return;
    int r = g_rowptr[idx] + g_boff[idx >> 10];
    g_rowptr[idx] = r;
    g_cursor[idx] = r;
}

__global__ void scatter_kernel(const void* __restrict__ ei) {
    int e = blockIdx.x * blockDim.x + threadIdx.x;
    if (e >= NT) return;
    int s, d;
    if (e < NE) { s = edge_idx(ei, 0, e); d = edge_idx(ei, 1, e); }
    else        { s = e - NE; d = s; }
    int pos = atomicAdd(&g_cursor[d], 1);
    g_csr_src[pos] = s;
}

// ---------------- layer1 GEMM: 64-node x 128-col block tile, 4x8 register tiles ----------------
// thread (tx = t&15, ty = t>>4): nodes nbase+ty*4..+3, cols tx*8..tx*8+7.
// x staged in padded shared (LDS.128 per 4 k's per node); W via LDG.128 (L1-resident).
__global__ void __launch_bounds__(256, 2) gemm1_kernel(const float* __restrict__ x,
                             const float* __restrict__ W,
                             const float* __restrict__ a_src,
                             const float* __restrict__ a_dst) {
    __shared__ float xs[64][XPAD];     // ~35KB
    int t = threadIdx.x;
    int tx = t & 15, ty = t >> 4;
    int nbase = blockIdx.x * 64;

    for (int i = t; i < 64 * 32; i += 256) {
        int n = i >> 5, kc = i & 31;
        int node = nbase + n;
        float4 v = (node < NN) ? ((const float4*)(x + (size_t)node * 128))[kc]
                               : make_float4(0.f, 0.f, 0.f, 0.f);
        *(float4*)&xs[n][kc * 4] = v;
    }
    __syncthreads();

    unsigned long long acc[4][4] = {};   // [node j][col-pair p] -> cols tx*8+2p, +1
    const ulonglong2* Wp = (const ulonglong2*)W;   // ulonglong2 = 4 floats; row k col c -> (k*128+c)/4
#pragma unroll 2
    for (int k4 = 0; k4 < 128; k4 += 4) {
        float4 xv[4];
#pragma unroll
        for (int j = 0; j < 4; j++) xv[j] = *(const float4*)&xs[ty * 4 + j][k4];
#pragma unroll
        for (int kk = 0; kk < 4; kk++) {
            int k = k4 + kk;
            ulonglong2 w01 = Wp[k * 32 + tx * 2];       // cols tx*8 .. +3
            ulonglong2 w23 = Wp[k * 32 + tx * 2 + 1];   // cols tx*8+4 .. +7
#pragma unroll
            for (int j = 0; j < 4; j++) {
                float xf = (kk == 0) ? xv[j].x : (kk == 1) ? xv[j].y
                         : (kk == 2) ? xv[j].z : xv[j].w;
                unsigned long long xp = pack2(xf);
                acc[j][0] = fma2(xp, w01.x, acc[j][0]);
                acc[j][1] = fma2(xp, w01.y, acc[j][1]);
                acc[j][2] = fma2(xp, w23.x, acc[j][2]);
                acc[j][3] = fma2(xp, w23.y, acc[j][3]);
            }
        }
    }

    int h  = tx >> 2;            // head owning cols tx*8..
    int co = (tx & 3) * 8;       // offset within head
    float4 as0 = *(const float4*)(a_src + h * 32 + co);
    float4 as1 = *(const float4*)(a_src + h * 32 + co + 4);
    float4 ad0 = *(const float4*)(a_dst + h * 32 + co);
    float4 ad1 = *(const float4*)(a_dst + h * 32 + co + 4);

#pragma unroll
    for (int j = 0; j < 4; j++) {
        int node = nbase + ty * 4 + j;
        float f0, f1, f2, f3, f4, f5, f6, f7;
        unpack2(acc[j][0], f0, f1);
        unpack2(acc[j][1], f2, f3);
        unpack2(acc[j][2], f4, f5);
        unpack2(acc[j][3], f6, f7);
        if (node < NN) {
            ulonglong2* hp = (ulonglong2*)(g_h1 + (size_t)node * 128 + tx * 8);
            hp[0] = make_ulonglong2(acc[j][0], acc[j][1]);
            hp[1] = make_ulonglong2(acc[j][2], acc[j][3]);
        }
        float ps = f0 * as0.x + f1 * as0.y + f2 * as0.z + f3 * as0.w
                 + f4 * as1.x + f5 * as1.y + f6 * as1.z + f7 * as1.w;
        float pd = f0 * ad0.x + f1 * ad0.y + f2 * ad0.z + f3 * ad0.w
                 + f4 * ad1.x + f5 * ad1.y + f6 * ad1.z + f7 * ad1.w;
        ps += __shfl_xor_sync(0xffffffff, ps, 1);
        ps += __shfl_xor_sync(0xffffffff, ps, 2);
        pd += __shfl_xor_sync(0xffffffff, pd, 1);
        pd += __shfl_xor_sync(0xffffffff, pd, 2);
        if ((tx & 3) == 0 && node < NN) {
            g_ssrc1[node * 4 + h] = ps;
            g_sdst1[node * 4 + h] = pd;
        }
    }
}

// ---------------- layer1 fused softmax + aggregation (warp per node) ----------------
__global__ void agg1_kernel(const float* __restrict__ bias) {
    __shared__ int   sh_s[8][32];
    __shared__ float sh_p[8][4][32];
    int w = threadIdx.x >> 5;
    int l = threadIdx.x & 31;
    int d = blockIdx.x * 8 + w;
    if (d >= NN) return;
    int start = g_rowptr[d];
    int end   = g_rowptr[d + 1];
    float4 sd = *(const float4*)(g_sdst1 + d * 4);
    int h = l >> 3;

    float4 m = make_float4(-CUDART_INF_F, -CUDART_INF_F, -CUDART_INF_F, -CUDART_INF_F);
    for (int i = start + l; i < end; i += 32) {
        int s = g_csr_src[i];
        float4 ss = *(const float4*)(g_ssrc1 + s * 4);
        m.x = fmaxf(m.x, lrelu(ss.x + sd.x));
        m.y = fmaxf(m.y, lrelu(ss.y + sd.y));
        m.z = fmaxf(m.z, lrelu(ss.z + sd.z));
        m.w = fmaxf(m.w, lrelu(ss.w + sd.w));
    }
#pragma unroll
    for (int o = 16; o; o >>= 1) {
        m.x = fmaxf(m.x, __shfl_xor_sync(0xffffffff, m.x, o));
        m.y = fmaxf(m.y, __shfl_xor_sync(0xffffffff, m.y, o));
        m.z = fmaxf(m.z, __shfl_xor_sync(0xffffffff, m.z, o));
        m.w = fmaxf(m.w, __shfl_xor_sync(0xffffffff, m.w, o));
    }

    unsigned long long acc01 = 0ull, acc23 = 0ull;
    float4 den = make_float4(0.f, 0.f, 0.f, 0.f);
    for (int base = start; base < end; base += 32) {
        int i = base + l;
        int s_l = 0;
        float4 p_l = make_float4(0.f, 0.f, 0.f, 0.f);
        if (i < end) {
            s_l = g_csr_src[i];
            float4 ss = *(const float4*)(g_ssrc1 + s_l * 4);
            p_l.x = __expf(lrelu(ss.x + sd.x) - m.x);
            p_l.y = __expf(lrelu(ss.y + sd.y) - m.y);
            p_l.z = __expf(lrelu(ss.z + sd.z) - m.z);
            p_l.w = __expf(lrelu(ss.w + sd.w) - m.w);
            den.x += p_l.x; den.y += p_l.y; den.z += p_l.z; den.w += p_l.w;
        }
        sh_s[w][l] = s_l;
        sh_p[w][0][l] = p_l.x;
        sh_p[w][1][l] = p_l.y;
        sh_p[w][2][l] = p_l.z;
        sh_p[w][3][l] = p_l.w;
        __syncwarp();
        int cnt = min(32, end - base);
        for (int j = 0; j < cnt; j++) {
            int   s  = sh_s[w][j];
            float ph = sh_p[w][h][j];
            ulonglong2 hv = *(const ulonglong2*)(g_h1 + (size_t)s * 128 + 4 * l);
            unsigned long long p2 = pack2(ph);
            acc01 = fma2(p2, hv.x, acc01);
            acc23 = fma2(p2, hv.y, acc23);
        }
        __syncwarp();
    }
#pragma unroll
    for (int o = 16; o; o >>= 1) {
        den.x += __shfl_xor_sync(0xffffffff, den.x, o);
        den.y += __shfl_xor_sync(0xffffffff, den.y, o);
        den.z += __shfl_xor_sync(0xffffffff, den.z, o);
        den.w += __shfl_xor_sync(0xffffffff, den.w, o);
    }
    float denh = (h == 0) ? den.x : (h == 1) ? den.y : (h == 2) ? den.z : den.w;

    float a0, a1, a2, a3;
    unpack2(acc01, a0, a1);
    unpack2(acc23, a2, a3);
    float4 bv = *(const float4*)(bias + 4 * l);
    float4 o;
    o.x = fmaxf(a0 / denh + bv.x, 0.f);
    o.y = fmaxf(a1 / denh + bv.y, 0.f);
    o.z = fmaxf(a2 / denh + bv.z, 0.f);
    o.w = fmaxf(a3 / denh + bv.w, 0.f);
    ((float4*)(g_out1 + (size_t)d * 128))[l] = o;
}

// ---------------- layer2 GEMM: 64-node x 64-col block tile, 4x4 register tiles ----------------
__global__ void __launch_bounds__(256, 2) gemm2_kernel(const float* __restrict__ W,
                             const float* __restrict__ a_src,
                             const float* __restrict__ a_dst) {
    __shared__ float xs[64][XPAD];
    int t = threadIdx.x;
    int tx = t & 15, ty = t >> 4;
    int nbase = blockIdx.x * 64;

    for (int i = t; i < 64 * 32; i += 256) {
        int n = i >> 5, kc = i & 31;
        int node = nbase + n;
        float4 v = (node < NN) ? ((const float4*)(g_out1 + (size_t)node * 128))[kc]
                               : make_float4(0.f, 0.f, 0.f, 0.f);
        *(float4*)&xs[n][kc * 4] = v;
    }
    __syncthreads();

    unsigned long long acc[4][2] = {};   // [node j][pair p] -> cols tx*4+2p, +1
    const ulonglong2* Wp = (const ulonglong2*)W;   // row k col c -> (k*64+c)/4
#pragma unroll 2
    for (int k4 = 0; k4 < 128; k4 += 4) {
        float4 xv[4];
#pragma unroll
        for (int j = 0; j < 4; j++) xv[j] = *(const float4*)&xs[ty * 4 + j][k4];
#pragma unroll
        for (int kk = 0; kk < 4; kk++) {
            int k = k4 + kk;
            ulonglong2 wv = Wp[k * 16 + tx];   // cols tx*4 .. +3
#pragma unroll
            for (int j = 0; j < 4; j++) {
                float xf = (kk == 0) ? xv[j].x : (kk == 1) ? xv[j].y
                         : (kk == 2) ? xv[j].z : xv[j].w;
                unsigned long long xp = pack2(xf);
                acc[j][0] = fma2(xp, wv.x, acc[j][0]);
                acc[j][1] = fma2(xp, wv.y, acc[j][1]);
            }
        }
    }

    float4 as = *(const float4*)(a_src + tx * 4);
    float4 ad = *(const float4*)(a_dst + tx * 4);
#pragma unroll
    for (int j = 0; j < 4; j++) {
        int node = nbase + ty * 4 + j;
        float f0, f1, f2, f3;
        unpack2(acc[j][0], f0, f1);
        unpack2(acc[j][1], f2, f3);
        if (node < NN) {
            *(ulonglong2*)(g_h2 + (size_t)node * 64 + tx * 4) =
                make_ulonglong2(acc[j][0], acc[j][1]);
        }
        float ps = f0 * as.x + f1 * as.y + f2 * as.z + f3 * as.w;
        float pd = f0 * ad.x + f1 * ad.y + f2 * ad.z + f3 * ad.w;
#pragma unroll
        for (int o = 1; o < 16; o <<= 1) {
            ps += __shfl_xor_sync(0xffffffff, ps, o);
            pd += __shfl_xor_sync(0xffffffff, pd, o);
        }
        if (tx == 0 && node < NN) {
            g_ssrc2[node] = ps;
            g_sdst2[node] = pd;
        }
    }
}

// ---------------- layer2 fused softmax + aggregation -> output ----------------
__global__ void agg2_kernel(const float* __restrict__ bias, float* __restrict__ out) {
    __shared__ int   sh_s[8][32];
    __shared__ float sh_p[8][32];
    int w = threadIdx.x >> 5;
    int l = threadIdx.x & 31;
    int d = blockIdx.x * 8 + w;
    if (d >= NN) return;
    int start = g_rowptr[d];
    int end   = g_rowptr[d + 1];
    float sdv = g_sdst2[d];

    float m = -CUDART_INF_F;
    for (int i = start + l; i < end; i += 32) {
        int s = g_csr_src[i];
        m = fmaxf(m, lrelu(g_ssrc2[s] + sdv));
    }
#pragma unroll
    for (int o = 16; o; o >>= 1) m = fmaxf(m, __shfl_xor_sync(0xffffffff, m, o));

    unsigned long long acc = 0ull;
    float den = 0.f;
    for (int base = start; base < end; base += 32) {
        int i = base + l;
        int s_l = 0;
        float p_l = 0.f;
        if (i < end) {
            s_l = g_csr_src[i];
            p_l = __expf(lrelu(g_ssrc2[s_l] + sdv) - m);
            den += p_l;
        }
        sh_s[w][l] = s_l;
        sh_p[w][l] = p_l;
        __syncwarp();
        int cnt = min(32, end - base);
        for (int j = 0; j < cnt; j++) {
            int   s = sh_s[w][j];
            float p = sh_p[w][j];
            unsigned long long hv = *(const unsigned long long*)(g_h2 + (size_t)s * 64 + 2 * l);
            acc = fma2(pack2(p), hv, acc);
        }
        __syncwarp();
    }
#pragma unroll
    for (int o = 16; o; o >>= 1) den += __shfl_xor_sync(0xffffffff, den, o);

    float a0, a1;
    unpack2(acc, a0, a1);
    float2 bv = *(const float2*)(bias + 2 * l);
    float2 o2;
    o2.x = a0 / den + bv.x;
    o2.y = a1 / den + bv.y;
    *(float2*)(out + (size_t)d * 64 + 2 * l) = o2;
}

// ---------------- launch ----------------
extern "C" void kernel_launch(void* const* d_in, const int* in_sizes, int n_in,
                              void* d_out, int out_size) {
    const float* x     = (const float*)d_in[0];
    const void*  ei    = d_in[1];
    const float* W1    = (const float*)d_in[2];
    const float* asrc1 = (const float*)d_in[3];
    const float* adst1 = (const float*)d_in[4];
    const float* b1    = (const float*)d_in[5];
    const float* W2    = (const float*)d_in[6];
    const float* asrc2 = (const float*)d_in[7];
    const float* adst2 = (const float*)d_in[8];
    const float* b2    = (const float*)d_in[9];
    float* out = (float*)d_out;

    const int T = 256;
    const int NBG = (NN + 63) / 64;
    detect_dtype<<<1, 128>>>((const unsigned int*)ei);
    zero_cnt<<<(NN + T - 1) / T, T>>>();
    hist_kernel<<<(NT + T - 1) / T, T>>>(ei);
    gemm1_kernel<<<NBG, 256>>>(x, W1, asrc1, adst1);   // 4th launch -> profiled
    scan1_kernel<<<NB_SCAN, 1024>>>();
    scan2_kernel<<<1, 64>>>();
    scan3_kernel<<<(NN + T - 1) / T, T>>>();
    scatter_kernel<<<(NT + T - 1) / T, T>>>(ei);
    agg1_kernel<<<(NN + 7) / 8, 256>>>(b1);
    gemm2_kernel<<<NBG, 256>>>(W2, asrc2, adst2);
    agg2_kernel<<<(NN + 7) / 8, 256>>>(b2, out);
}

// round 9
// speedup vs baseline: 2.5727x; 1.1054x over previous
#include <cuda_runtime.h>
#include <cuda_bf16.h>
#include <math_constants.h>

#define NN 50000                 // nodes
#define NE 800000                // raw edges
#define NT (NE + NN)             // edges + self loops
#define NEG_SLOPE 0.2f
#define NB_SCAN ((NN + 1023) / 1024)   // 49 scan blocks
#define XPAD 132                 // padded shared row stride (floats), 16B aligned

// ---------------- scratch ----------------
__device__ float g_h1[NN * 128];
__device__ float g_ssrc1[NN * 4];
__device__ float g_sdst1[NN * 4];
__device__ float g_out1[NN * 128];
__device__ float g_h2[NN * 64];
__device__ float g_ssrc2[NN];
__device__ float g_sdst2[NN];
__device__ int   g_cnt[NN];
__device__ int   g_rowptr[NN + 1];
__device__ int   g_cursor[NN];
__device__ int   g_csr_src[NT];
__device__ int   g_bsum[64];
__device__ int   g_boff[64];
__device__ int   g_is64;

// ---------------- helpers ----------------
__device__ __forceinline__ float lrelu(float v) { return v > 0.f ? v : NEG_SLOPE * v; }

__device__ __forceinline__ int edge_idx(const void* ei, int row, int e) {
    if (g_is64) return (int)((const long long*)ei)[(size_t)row * NE + e];
    else        return ((const int*)ei)[(size_t)row * NE + e];
}

// packed f32x2 helpers (Blackwell FFMA2 — only via PTX)
__device__ __forceinline__ unsigned long long pack2(float f) {
    unsigned long long r;
    asm("mov.b64 %0, {%1, %1};" : "=l"(r) : "f"(f));
    return r;
}
__device__ __forceinline__ unsigned long long fma2(unsigned long long a,
                                                   unsigned long long b,
                                                   unsigned long long c) {
    unsigned long long d;
    asm("fma.rn.f32x2 %0, %1, %2, %3;" : "=l"(d) : "l"(a), "l"(b), "l"(c));
    return d;
}
__device__ __forceinline__ void unpack2(unsigned long long v, float& lo, float& hi) {
    asm("mov.b64 {%0, %1}, %2;" : "=f"(lo), "=f"(hi) : "l"(v));
}

// ---------------- dtype detection ----------------
__global__ void detect_dtype(const unsigned int* __restrict__ ei_words) {
    __shared__ int any_nonzero;
    if (threadIdx.x == 0) any_nonzero = 0;
    __syncthreads();
    unsigned int w = ei_words[2 * threadIdx.x + 1];
    if (w != 0u) atomicOr(&any_nonzero, 1);
    __syncthreads();
    if (threadIdx.x == 0) g_is64 = any_nonzero ? 0 : 1;
}

// ---------------- CSR build ----------------
__global__ void zero_cnt() {
    int i = blockIdx.x * blockDim.x + threadIdx.x;
    if (i < NN) g_cnt[i] = 0;
}

__global__ void hist_kernel(const void* __restrict__ ei) {
    int e = blockIdx.x * blockDim.x + threadIdx.x;
    if (e >= NT) return;
    int d = (e < NE) ? edge_idx(ei, 1, e) : (e - NE);
    atomicAdd(&g_cnt[d], 1);
}

__global__ void scan1_kernel() {
    __shared__ int wsum[32];
    int t = threadIdx.x;
    int idx = blockIdx.x * 1024 + t;
    int v = (idx < NN) ? g_cnt[idx] : 0;
    int incl = v;
#pragma unroll
    for (int o = 1; o < 32; o <<= 1) {
        int nbr = __shfl_up_sync(0xffffffff, incl, o);
        if ((t & 31) >= o) incl += nbr;
    }
    if ((t & 31) == 31) wsum[t >> 5] = incl;
    __syncthreads();
    if (t < 32) {
        int ws = wsum[t];
        int wincl = ws;
#pragma unroll
        for (int o = 1; o < 32; o <<= 1) {
            int nbr = __shfl_up_sync(0xffffffff, wincl, o);
            if (t >= o) wincl += nbr;
        }
        wsum[t] = wincl - ws;
    }
    __syncthreads();
    int excl = incl - v + wsum[t >> 5];
    if (idx < NN) g_rowptr[idx] = excl;
    if (t == 1023) g_bsum[blockIdx.x] = excl + v;
}

__global__ void scan2_kernel() {
    __shared__ int s[64];
    int t = threadIdx.x;
    int v = (t < NB_SCAN) ? g_bsum[t] : 0;
    s[t] = v;
    __syncthreads();
#pragma unroll
    for (int o = 1; o < 64; o <<= 1) {
        int tmp = (t >= o) ? s[t - o] : 0;
        __syncthreads();
        s[t] += tmp;
        __syncthreads();
    }
    g_boff[t] = s[t] - v;
}

__global__ void scan3_kernel() {
    int idx = blockIdx.x * blockDim.x + threadIdx.x;
    if (idx == 0) g_rowptr[NN] = NT;
    if (idx >= NN) return;
    int r = g_rowptr[idx] + g_boff[idx >> 10];
    g_rowptr[idx] = r;
    g_cursor[idx] = r;
}

__global__ void scatter_kernel(const void* __restrict__ ei) {
    int e = blockIdx.x * blockDim.x + threadIdx.x;
    if (e >= NT) return;
    int s, d;
    if (e < NE) { s = edge_idx(ei, 0, e); d = edge_idx(ei, 1, e); }
    else        { s = e - NE; d = s; }
    int pos = atomicAdd(&g_cursor[d], 1);
    g_csr_src[pos] = s;
}

// ---------------- layer1 GEMM: 64-node tile; warp = 8 nodes, lane = 4 cols ----------------
// Warp ty (0..7) owns nodes nbase+ty*8 .. +7; lane tx owns cols 4tx..4tx+3.
// Per k per warp: 1 LDG.128 of W (512B dense = 4 wavefronts); x via broadcast LDS.
__global__ void __launch_bounds__(256, 2) gemm1_kernel(const float* __restrict__ x,
                             const float* __restrict__ W,
                             const float* __restrict__ a_src,
                             const float* __restrict__ a_dst) {
    __shared__ float xs[64][XPAD];
    int t = threadIdx.x;
    int tx = t & 31, ty = t >> 5;
    int nbase = blockIdx.x * 64;

    for (int i = t; i < 64 * 32; i += 256) {
        int n = i >> 5, kc = i & 31;
        int node = nbase + n;
        float4 v = (node < NN) ? ((const float4*)(x + (size_t)node * 128))[kc]
                               : make_float4(0.f, 0.f, 0.f, 0.f);
        *(float4*)&xs[n][kc * 4] = v;
    }
    __syncthreads();

    unsigned long long acc[8][2] = {};   // [node j][pair p] -> cols 4tx+2p, +1
    const ulonglong2* Wp = (const ulonglong2*)W;   // 4 floats; row k col c -> k*32 + c/4
#pragma unroll 2
    for (int k4 = 0; k4 < 128; k4 += 4) {
        float4 xv[8];
#pragma unroll
        for (int j = 0; j < 8; j++) xv[j] = *(const float4*)&xs[ty * 8 + j][k4];
#pragma unroll
        for (int kk = 0; kk < 4; kk++) {
            ulonglong2 wv = Wp[(k4 + kk) * 32 + tx];   // cols 4tx..4tx+3
#pragma unroll
            for (int j = 0; j < 8; j++) {
                float xf = (kk == 0) ? xv[j].x : (kk == 1) ? xv[j].y
                         : (kk == 2) ? xv[j].z : xv[j].w;
                unsigned long long xp = pack2(xf);
                acc[j][0] = fma2(xp, wv.x, acc[j][0]);
                acc[j][1] = fma2(xp, wv.y, acc[j][1]);
            }
        }
    }

    int h = tx >> 3;                      // head owning cols 4tx..
    float4 as = *(const float4*)(a_src + 4 * tx);
    float4 ad = *(const float4*)(a_dst + 4 * tx);

#pragma unroll
    for (int j = 0; j < 8; j++) {
        int node = nbase + ty * 8 + j;
        float f0, f1, f2, f3;
        unpack2(acc[j][0], f0, f1);
        unpack2(acc[j][1], f2, f3);
        if (node < NN) {
            *(ulonglong2*)(g_h1 + (size_t)node * 128 + 4 * tx) =
                make_ulonglong2(acc[j][0], acc[j][1]);
        }
        float ps = f0 * as.x + f1 * as.y + f2 * as.z + f3 * as.w;
        float pd = f0 * ad.x + f1 * ad.y + f2 * ad.z + f3 * ad.w;
        ps += __shfl_xor_sync(0xffffffff, ps, 1);
        ps += __shfl_xor_sync(0xffffffff, ps, 2);
        ps += __shfl_xor_sync(0xffffffff, ps, 4);
        pd += __shfl_xor_sync(0xffffffff, pd, 1);
        pd += __shfl_xor_sync(0xffffffff, pd, 2);
        pd += __shfl_xor_sync(0xffffffff, pd, 4);
        if ((tx & 7) == 0 && node < NN) {
            g_ssrc1[node * 4 + h] = ps;
            g_sdst1[node * 4 + h] = pd;
        }
    }
}

// ---------------- layer1 fused softmax + aggregation (warp per node) ----------------
__global__ void agg1_kernel(const float* __restrict__ bias) {
    __shared__ int   sh_s[8][32];
    __shared__ float sh_p[8][4][32];
    int w = threadIdx.x >> 5;
    int l = threadIdx.x & 31;
    int d = blockIdx.x * 8 + w;
    if (d >= NN) return;
    int start = g_rowptr[d];
    int end   = g_rowptr[d + 1];
    float4 sd = *(const float4*)(g_sdst1 + d * 4);
    int h = l >> 3;

    float4 m = make_float4(-CUDART_INF_F, -CUDART_INF_F, -CUDART_INF_F, -CUDART_INF_F);
    for (int i = start + l; i < end; i += 32) {
        int s = g_csr_src[i];
        float4 ss = *(const float4*)(g_ssrc1 + s * 4);
        m.x = fmaxf(m.x, lrelu(ss.x + sd.x));
        m.y = fmaxf(m.y, lrelu(ss.y + sd.y));
        m.z = fmaxf(m.z, lrelu(ss.z + sd.z));
        m.w = fmaxf(m.w, lrelu(ss.w + sd.w));
    }
#pragma unroll
    for (int o = 16; o; o >>= 1) {
        m.x = fmaxf(m.x, __shfl_xor_sync(0xffffffff, m.x, o));
        m.y = fmaxf(m.y, __shfl_xor_sync(0xffffffff, m.y, o));
        m.z = fmaxf(m.z, __shfl_xor_sync(0xffffffff, m.z, o));
        m.w = fmaxf(m.w, __shfl_xor_sync(0xffffffff, m.w, o));
    }

    unsigned long long acc01 = 0ull, acc23 = 0ull;
    float4 den = make_float4(0.f, 0.f, 0.f, 0.f);
    for (int base = start; base < end; base += 32) {
        int i = base + l;
        int s_l = 0;
        float4 p_l = make_float4(0.f, 0.f, 0.f, 0.f);
        if (i < end) {
            s_l = g_csr_src[i];
            float4 ss = *(const float4*)(g_ssrc1 + s_l * 4);
            p_l.x = __expf(lrelu(ss.x + sd.x) - m.x);
            p_l.y = __expf(lrelu(ss.y + sd.y) - m.y);
            p_l.z = __expf(lrelu(ss.z + sd.z) - m.z);
            p_l.w = __expf(lrelu(ss.w + sd.w) - m.w);
            den.x += p_l.x; den.y += p_l.y; den.z += p_l.z; den.w += p_l.w;
        }
        sh_s[w][l] = s_l;
        sh_p[w][0][l] = p_l.x;
        sh_p[w][1][l] = p_l.y;
        sh_p[w][2][l] = p_l.z;
        sh_p[w][3][l] = p_l.w;
        __syncwarp();
        int cnt = min(32, end - base);
        for (int j = 0; j < cnt; j++) {
            int   s  = sh_s[w][j];
            float ph = sh_p[w][h][j];
            ulonglong2 hv = *(const ulonglong2*)(g_h1 + (size_t)s * 128 + 4 * l);
            unsigned long long p2 = pack2(ph);
            acc01 = fma2(p2, hv.x, acc01);
            acc23 = fma2(p2, hv.y, acc23);
        }
        __syncwarp();
    }
#pragma unroll
    for (int o = 16; o; o >>= 1) {
        den.x += __shfl_xor_sync(0xffffffff, den.x, o);
        den.y += __shfl_xor_sync(0xffffffff, den.y, o);
        den.z += __shfl_xor_sync(0xffffffff, den.z, o);
        den.w += __shfl_xor_sync(0xffffffff, den.w, o);
    }
    float denh = (h == 0) ? den.x : (h == 1) ? den.y : (h == 2) ? den.z : den.w;

    float a0, a1, a2, a3;
    unpack2(acc01, a0, a1);
    unpack2(acc23, a2, a3);
    float4 bv = *(const float4*)(bias + 4 * l);
    float4 o;
    o.x = fmaxf(a0 / denh + bv.x, 0.f);
    o.y = fmaxf(a1 / denh + bv.y, 0.f);
    o.z = fmaxf(a2 / denh + bv.z, 0.f);
    o.w = fmaxf(a3 / denh + bv.w, 0.f);
    ((float4*)(g_out1 + (size_t)d * 128))[l] = o;
}

// ---------------- layer2 GEMM: 64-node tile; warp = 8 nodes, lane = 2 cols ----------------
__global__ void __launch_bounds__(256, 2) gemm2_kernel(const float* __restrict__ W,
                             const float* __restrict__ a_src,
                             const float* __restrict__ a_dst) {
    __shared__ float xs[64][XPAD];
    int t = threadIdx.x;
    int tx = t & 31, ty = t >> 5;
    int nbase = blockIdx.x * 64;

    for (int i = t; i < 64 * 32; i += 256) {
        int n = i >> 5, kc = i & 31;
        int node = nbase + n;
        float4 v = (node < NN) ? ((const float4*)(g_out1 + (size_t)node * 128))[kc]
                               : make_float4(0.f, 0.f, 0.f, 0.f);
        *(float4*)&xs[n][kc * 4] = v;
    }
    __syncthreads();

    unsigned long long acc[8] = {};   // node j -> cols 2tx, 2tx+1
    const unsigned long long* Wp = (const unsigned long long*)W;   // row k col c -> k*32 + c/2
#pragma unroll 2
    for (int k4 = 0; k4 < 128; k4 += 4) {
        float4 xv[8];
#pragma unroll
        for (int j = 0; j < 8; j++) xv[j] = *(const float4*)&xs[ty * 8 + j][k4];
#pragma unroll
        for (int kk = 0; kk < 4; kk++) {
            unsigned long long wv = Wp[(k4 + kk) * 32 + tx];   // cols 2tx, 2tx+1
#pragma unroll
            for (int j = 0; j < 8; j++) {
                float xf = (kk == 0) ? xv[j].x : (kk == 1) ? xv[j].y
                         : (kk == 2) ? xv[j].z : xv[j].w;
                acc[j] = fma2(pack2(xf), wv, acc[j]);
            }
        }
    }

    float2 as = *(const float2*)(a_src + 2 * tx);
    float2 ad = *(const float2*)(a_dst + 2 * tx);
#pragma unroll
    for (int j = 0; j < 8; j++) {
        int node = nbase + ty * 8 + j;
        float f0, f1;
        unpack2(acc[j], f0, f1);
        if (node < NN) {
            *(unsigned long long*)(g_h2 + (size_t)node * 64 + 2 * tx) = acc[j];
        }
        float ps = f0 * as.x + f1 * as.y;
        float pd = f0 * ad.x + f1 * ad.y;
#pragma unroll
        for (int o = 1; o < 32; o <<= 1) {
            ps += __shfl_xor_sync(0xffffffff, ps, o);
            pd += __shfl_xor_sync(0xffffffff, pd, o);
        }
        if (tx == 0 && node < NN) {
            g_ssrc2[node] = ps;
            g_sdst2[node] = pd;
        }
    }
}

// ---------------- layer2 fused softmax + aggregation -> output ----------------
__global__ void agg2_kernel(const float* __restrict__ bias, float* __restrict__ out) {
    __shared__ int   sh_s[8][32];
    __shared__ float sh_p[8][32];
    int w = threadIdx.x >> 5;
    int l = threadIdx.x & 31;
    int d = blockIdx.x * 8 + w;
    if (d >= NN) return;
    int start = g_rowptr[d];
    int end   = g_rowptr[d + 1];
    float sdv = g_sdst2[d];

    float m = -CUDART_INF_F;
    for (int i = start + l; i < end; i += 32) {
        int s = g_csr_src[i];
        m = fmaxf(m, lrelu(g_ssrc2[s] + sdv));
    }
#pragma unroll
    for (int o = 16; o; o >>= 1) m = fmaxf(m, __shfl_xor_sync(0xffffffff, m, o));

    unsigned long long acc = 0ull;
    float den = 0.f;
    for (int base = start; base < end; base += 32) {
        int i = base + l;
        int s_l = 0;
        float p_l = 0.f;
        if (i < end) {
            s_l = g_csr_src[i];
            p_l = __expf(lrelu(g_ssrc2[s_l] + sdv) - m);
            den += p_l;
        }
        sh_s[w][l] = s_l;
        sh_p[w][l] = p_l;
        __syncwarp();
        int cnt = min(32, end - base);
        for (int j = 0; j < cnt; j++) {
            int   s = sh_s[w][j];
            float p = sh_p[w][j];
            unsigned long long hv = *(const unsigned long long*)(g_h2 + (size_t)s * 64 + 2 * l);
            acc = fma2(pack2(p), hv, acc);
        }
        __syncwarp();
    }
#pragma unroll
    for (int o = 16; o; o >>= 1) den += __shfl_xor_sync(0xffffffff, den, o);

    float a0, a1;
    unpack2(acc, a0, a1);
    float2 bv = *(const float2*)(bias + 2 * l);
    float2 o2;
    o2.x = a0 / den + bv.x;
    o2.y = a1 / den + bv.y;
    *(float2*)(out + (size_t)d * 64 + 2 * l) = o2;
}

// ---------------- launch ----------------
extern "C" void kernel_launch(void* const* d_in, const int* in_sizes, int n_in,
                              void* d_out, int out_size) {
    const float* x     = (const float*)d_in[0];
    const void*  ei    = d_in[1];
    const float* W1    = (const float*)d_in[2];
    const float* asrc1 = (const float*)d_in[3];
    const float* adst1 = (const float*)d_in[4];
    const float* b1    = (const float*)d_in[5];
    const float* W2    = (const float*)d_in[6];
    const float* asrc2 = (const float*)d_in[7];
    const float* adst2 = (const float*)d_in[8];
    const float* b2    = (const float*)d_in[9];
    float* out = (float*)d_out;

    const int T = 256;
    const int NBG = (NN + 63) / 64;
    detect_dtype<<<1, 128>>>((const unsigned int*)ei);
    zero_cnt<<<(NN + T - 1) / T, T>>>();
    hist_kernel<<<(NT + T - 1) / T, T>>>(ei);
    gemm1_kernel<<<NBG, 256>>>(x, W1, asrc1, adst1);   // 4th launch -> profiled
    scan1_kernel<<<NB_SCAN, 1024>>>();
    scan2_kernel<<<1, 64>>>();
    scan3_kernel<<<(NN + T - 1) / T, T>>>();
    scatter_kernel<<<(NT + T - 1) / T, T>>>(ei);
    agg1_kernel<<<(NN + 7) / 8, 256>>>(b1);
    gemm2_kernel<<<NBG, 256>>>(W2, asrc2, adst2);
    agg2_kernel<<<(NN + 7) / 8, 256>>>(b2, out);
}